// round 11
// baseline (speedup 1.0000x reference)
#include <cuda_runtime.h>
#include <cuda_fp16.h>
#include <cstdint>

// ===================== problem constants =====================
#define NTOK  16384          // B*N tokens
#define DIM   1024
#define EDIM  3072           // 3*DIM
#define BATCH 4
#define SEQ   4096
#define NSEG  32
#define SEGL  128            // SEQ / NSEG

// ===================== device scratch (no cudaMalloc allowed) ==========
__device__ __half g_ha[(size_t)NTOK * DIM];    // fp16 activations
__device__ __half g_wh[(size_t)EDIM * DIM];    // fp16 weights
__device__ __half g_qkva[(size_t)NTOK * EDIM]; // GEMM output [tok][3d], fp16
__device__ float  g_sumA[BATCH * NSEG * DIM];  // per-segment gate products
__device__ float  g_sumY[BATCH * NSEG * DIM];  // per-segment local scan tails
__device__ float  g_carry[BATCH * NSEG * DIM]; // exclusive carry entering each segment

// ===================== PTX helpers (all valid on compute_103) ==========
__device__ __forceinline__ uint32_t smem_u32(const void* p) {
    uint32_t r;
    asm("{ .reg .u64 t; cvta.to.shared.u64 t, %1; cvt.u32.u64 %0, t; }" : "=r"(r) : "l"(p));
    return r;
}
__device__ __forceinline__ void cp16(uint32_t dst, const void* src) {
    asm volatile("cp.async.cg.shared.global [%0], [%1], 16;" :: "r"(dst), "l"(src));
}
#define CP_COMMIT() asm volatile("cp.async.commit_group;" ::: "memory")
#define CP_WAIT2()  asm volatile("cp.async.wait_group 2;" ::: "memory")

__device__ __forceinline__ void ldm_x4(uint32_t* r, uint32_t addr) {
    asm volatile("ldmatrix.sync.aligned.m8n8.x4.shared.b16 {%0,%1,%2,%3}, [%4];"
                 : "=r"(r[0]), "=r"(r[1]), "=r"(r[2]), "=r"(r[3]) : "r"(addr));
}
__device__ __forceinline__ void mma16816(float* c, const uint32_t* a, const uint32_t* b) {
    asm volatile(
        "mma.sync.aligned.m16n8k16.row.col.f32.f16.f16.f32 "
        "{%0,%1,%2,%3}, {%4,%5,%6,%7}, {%8,%9}, {%0,%1,%2,%3};"
        : "+f"(c[0]), "+f"(c[1]), "+f"(c[2]), "+f"(c[3])
        : "r"(a[0]), "r"(a[1]), "r"(a[2]), "r"(a[3]), "r"(b[0]), "r"(b[1]));
}

// ===================== kernel 1: RMSNorm -> fp16 activations ==============
__global__ void rmsnorm_kernel(const float* __restrict__ x, const float* __restrict__ gamma) {
    __shared__ float red[8];
    const int tok = blockIdx.x;
    const int tid = threadIdx.x;   // 256 threads, 4 elems each
    float4 v = ((const float4*)(x + (size_t)tok * DIM))[tid];
    float s = v.x * v.x + v.y * v.y + v.z * v.z + v.w * v.w;
    #pragma unroll
    for (int o = 16; o; o >>= 1) s += __shfl_xor_sync(0xffffffffu, s, o);
    if ((tid & 31) == 0) red[tid >> 5] = s;
    __syncthreads();
    if (tid == 0) {
        float t = 0.f;
        #pragma unroll
        for (int i = 0; i < 8; i++) t += red[i];
        red[0] = 32.0f / fmaxf(sqrtf(t), 1e-12f);   // sqrt(DIM)=32
    }
    __syncthreads();
    const float scl = red[0];
    float4 g = ((const float4*)gamma)[tid];
    __half2* hh = (__half2*)(g_ha + (size_t)tok * DIM);
    hh[2 * tid]     = __floats2half2_rn(v.x * scl * g.x, v.y * scl * g.y);
    hh[2 * tid + 1] = __floats2half2_rn(v.z * scl * g.z, v.w * scl * g.w);
}

// ===================== kernel 2: weight convert -> fp16 ====================
__global__ void wconv_kernel(const float* __restrict__ w) {
    size_t i4 = (size_t)blockIdx.x * 256 + threadIdx.x;   // EDIM*DIM/4 float4s
    float4 v = ((const float4*)w)[i4];
    ((__half2*)g_wh)[2 * i4]     = __floats2half2_rn(v.x, v.y);
    ((__half2*)g_wh)[2 * i4 + 1] = __floats2half2_rn(v.z, v.w);
}

// ===================== kernel 3: HMMA GEMM, CTA 128x128, 4 warps 64x64 =====
// qkva[m][e] = sum_d h[m][d]*w[e][d]; BK=32, 4-stage cp.async, 2 CTAs/SM,
// register-double-buffered fragments, fp16 output.
#define PITCHB 80
#define TILEB  (128 * PITCHB)          // 10240
#define OFF_A  0
#define OFF_B  TILEB
#define STAGEB (2 * TILEB)             // 20480
#define NSTAGE 4
#define NKC    32                      // 1024 / 32
#define GEMM_SMEM (NSTAGE * STAGEB)    // 81920 -> 2 CTAs/SM

__device__ __forceinline__ void load_stage(uint32_t sm_stage,
                                           const __half* A, const __half* B,
                                           int koff, int tid) {
    #pragma unroll
    for (int i = 0; i < 4; i++) {
        const int c   = tid + i * 128;       // 0..511
        const int row = c >> 2;
        const int kc4 = c & 3;
        const uint32_t so = (uint32_t)(row * PITCHB + kc4 * 16);
        const size_t   go = (size_t)row * DIM + koff + kc4 * 8;
        cp16(sm_stage + OFF_A + so, A + go);
        cp16(sm_stage + OFF_B + so, B + go);
    }
}

// Load one (stage, step) worth of fragments: A 4x ldm_x4, B 4x ldm_x4.
__device__ __forceinline__ void load_frags(uint32_t* ah, uint32_t* bf,
                                           uint32_t sb, uint32_t a_base, uint32_t b_base,
                                           int step) {
    #pragma unroll
    for (int mt = 0; mt < 4; mt++)
        ldm_x4(ah + 4 * mt, sb + OFF_A + a_base + step * 32 + mt * 16 * PITCHB);
    #pragma unroll
    for (int p = 0; p < 4; p++)
        ldm_x4(bf + 4 * p, sb + OFF_B + b_base + step * 32 + p * 16 * PITCHB);
}

__global__ void __launch_bounds__(128, 2) gemm_kernel() {
    extern __shared__ char smem[];
    const uint32_t smem_base = smem_u32(smem);
    const int tid  = threadIdx.x;
    const int wid  = tid >> 5;       // 0..3
    const int lane = tid & 31;
    const int warp_m = wid >> 1;     // 0..1 -> 64-row strip
    const int warp_n = wid & 1;      // 0..1 -> 64-col strip
    const int ntile = blockIdx.x;    // 0..23 (fast dim -> A tile hot in L2)
    const int mtile = blockIdx.y;    // 0..127

    const __half* A = g_ha + (size_t)(mtile * 128) * DIM;
    const __half* B = g_wh + (size_t)(ntile * 128) * DIM;

    #pragma unroll
    for (int s = 0; s < NSTAGE - 1; s++) {
        load_stage(smem_base + s * STAGEB, A, B, s * 32, tid);
        CP_COMMIT();
    }

    float acc[4][8][4];
    #pragma unroll
    for (int mt = 0; mt < 4; mt++)
        #pragma unroll
        for (int nt = 0; nt < 8; nt++)
            #pragma unroll
            for (int r = 0; r < 4; r++) acc[mt][nt][r] = 0.f;

    const uint32_t a_base = (uint32_t)((warp_m * 64 + (lane & 15)) * PITCHB) + ((lane >> 4) << 4);
    const uint32_t b_base = (uint32_t)((warp_n * 64 + ((lane >> 4) << 3) + (lane & 7)) * PITCHB)
                          + (((lane >> 3) & 1) << 4);

    uint32_t ah[2][16], bf[2][16];   // double-buffered per (kc,step)

    CP_WAIT2();
    __syncthreads();
    load_frags(ah[0], bf[0], smem_base, a_base, b_base, 0);

    for (int kc = 0; kc < NKC; kc++) {
        const uint32_t sb = smem_base + (kc & (NSTAGE - 1)) * STAGEB;
        if (kc + NSTAGE - 1 < NKC)
            load_stage(smem_base + ((kc + NSTAGE - 1) & (NSTAGE - 1)) * STAGEB,
                       A, B, (kc + NSTAGE - 1) * 32, tid);
        CP_COMMIT();

        // prefetch (kc, step1) into buf1 (same stage: no barrier needed)
        load_frags(ah[1], bf[1], sb, a_base, b_base, 1);

        // MMAs for (kc, step0)
        #pragma unroll
        for (int nt = 0; nt < 8; nt++)
            #pragma unroll
            for (int mt = 0; mt < 4; mt++)
                mma16816(acc[mt][nt], &ah[0][4 * mt], &bf[0][2 * nt]);

        // stage barrier for kc+1, then prefetch (kc+1, step0) into buf0
        if (kc + 1 < NKC) {
            CP_WAIT2();
            __syncthreads();
            const uint32_t sbn = smem_base + ((kc + 1) & (NSTAGE - 1)) * STAGEB;
            load_frags(ah[0], bf[0], sbn, a_base, b_base, 0);
        }

        // MMAs for (kc, step1)
        #pragma unroll
        for (int nt = 0; nt < 8; nt++)
            #pragma unroll
            for (int mt = 0; mt < 4; mt++)
                mma16816(acc[mt][nt], &ah[1][4 * mt], &bf[1][2 * nt]);
    }

    // fp16 epilogue
    const int gid = lane >> 2, qid = lane & 3;
    #pragma unroll
    for (int mt = 0; mt < 4; mt++) {
        const int row0 = mtile * 128 + warp_m * 64 + mt * 16 + gid;
        #pragma unroll
        for (int nt = 0; nt < 8; nt++) {
            const int col = ntile * 128 + warp_n * 64 + nt * 8 + qid * 2;
            *(__half2*)(g_qkva + (size_t)row0 * EDIM + col) =
                __floats2half2_rn(acc[mt][nt][0], acc[mt][nt][1]);
            *(__half2*)(g_qkva + (size_t)(row0 + 8) * EDIM + col) =
                __floats2half2_rn(acc[mt][nt][2], acc[mt][nt][3]);
        }
    }
}

// ===================== kernel 4: scan pass A (local segment summaries) =====
// 2 channels/thread via half2. grid (DIM/512, NSEG, BATCH) x 256 threads.
__global__ void __launch_bounds__(256) scanA_kernel() {
    const int tid = threadIdx.x;
    const int d0  = blockIdx.x * 512 + tid * 2;
    const int seg = blockIdx.y;
    const int b   = blockIdx.z;
    const size_t tok0 = (size_t)b * SEQ + (size_t)seg * SEGL;
    const __half* base_kv = g_qkva + tok0 * EDIM + DIM + d0;
    const __half* base_av = g_qkva + tok0 * EDIM + 2 * DIM + d0;
    float pa0 = 1.f, pa1 = 1.f, y0 = 0.f, y1 = 0.f;
    #pragma unroll 8
    for (int i = 0; i < SEGL; i++) {
        const float2 kv = __half22float2(*(const __half2*)(base_kv + (size_t)i * EDIM));
        const float2 av = __half22float2(*(const __half2*)(base_av + (size_t)i * EDIM));
        const float a0 = 1.0f / (1.0f + __expf(-av.x));
        const float a1 = 1.0f / (1.0f + __expf(-av.y));
        y0 = a0 * y0 + kv.x;  pa0 *= a0;
        y1 = a1 * y1 + kv.y;  pa1 *= a1;
    }
    const size_t sidx = (size_t)(b * NSEG + seg) * DIM + d0;
    *(float2*)&g_sumA[sidx] = make_float2(pa0, pa1);
    *(float2*)&g_sumY[sidx] = make_float2(y0, y1);
}

// ===================== kernel 5: scan pass B (summary scan, tiny) ==========
__global__ void __launch_bounds__(256) scanB_kernel() {
    const int idx = blockIdx.x * 256 + threadIdx.x;   // 0..4095
    const int b = idx >> 10;
    const int d = idx & (DIM - 1);
    float c = 0.f;
    #pragma unroll
    for (int s = 0; s < NSEG; s++) {
        const size_t i = (size_t)(b * NSEG + s) * DIM + d;
        g_carry[i] = c;                       // exclusive carry entering segment s
        c = g_sumA[i] * c + g_sumY[i];
    }
}

// ===================== kernel 6: scan pass C (recompute + q*y) =============
__global__ void __launch_bounds__(256) scanC_kernel(float* __restrict__ out) {
    const int tid = threadIdx.x;
    const int d0  = blockIdx.x * 512 + tid * 2;
    const int seg = blockIdx.y;
    const int b   = blockIdx.z;
    const size_t tok0 = (size_t)b * SEQ + (size_t)seg * SEGL;
    const __half* base_q  = g_qkva + tok0 * EDIM + d0;
    const __half* base_kv = g_qkva + tok0 * EDIM + DIM + d0;
    const __half* base_av = g_qkva + tok0 * EDIM + 2 * DIM + d0;
    float* outp = out + tok0 * DIM + d0;
    const float2 cin = *(const float2*)&g_carry[(size_t)(b * NSEG + seg) * DIM + d0];
    float y0 = cin.x, y1 = cin.y;
    #pragma unroll 8
    for (int i = 0; i < SEGL; i++) {
        const float2 kv = __half22float2(*(const __half2*)(base_kv + (size_t)i * EDIM));
        const float2 av = __half22float2(*(const __half2*)(base_av + (size_t)i * EDIM));
        const float2 q  = __half22float2(*(const __half2*)(base_q  + (size_t)i * EDIM));
        const float a0 = 1.0f / (1.0f + __expf(-av.x));
        const float a1 = 1.0f / (1.0f + __expf(-av.y));
        y0 = a0 * y0 + kv.x;
        y1 = a1 * y1 + kv.y;
        *(float2*)(outp + (size_t)i * DIM) = make_float2(q.x * y0, q.y * y1);
    }
}

// ===================== launcher =====================
extern "C" void kernel_launch(void* const* d_in, const int* in_sizes, int n_in,
                              void* d_out, int out_size) {
    const float* x     = (const float*)d_in[0];   // [4,4096,1024] f32
    const float* w     = (const float*)d_in[1];   // [3072,1024]  f32
    const float* gamma = (const float*)d_in[2];   // [1024]       f32
    float* out = (float*)d_out;

    cudaFuncSetAttribute(gemm_kernel, cudaFuncAttributeMaxDynamicSharedMemorySize, GEMM_SMEM);

    rmsnorm_kernel<<<NTOK, 256>>>(x, gamma);
    wconv_kernel<<<(EDIM * DIM / 4) / 256, 256>>>(w);
    gemm_kernel<<<dim3(EDIM / 128, NTOK / 128), 128, GEMM_SMEM>>>();
    scanA_kernel<<<dim3(DIM / 512, NSEG, BATCH), 256>>>();
    scanB_kernel<<<BATCH * DIM / 256, 256>>>();
    scanC_kernel<<<dim3(DIM / 512, NSEG, BATCH), 256>>>(out);
}

// round 12
// speedup vs baseline: 1.2127x; 1.2127x over previous
#include <cuda_runtime.h>
#include <cuda_fp16.h>
#include <cstdint>

// ===================== problem constants =====================
#define NTOK  16384          // B*N tokens
#define DIM   1024
#define EDIM  3072           // 3*DIM
#define BATCH 4
#define SEQ   4096
#define NSEG  128
#define SEGL  32             // SEQ / NSEG

// ===================== device scratch (no cudaMalloc allowed) ==========
__device__ __half g_ha[(size_t)NTOK * DIM];    // fp16 activations
__device__ __half g_wh[(size_t)EDIM * DIM];    // fp16 weights
__device__ __half g_qkva[(size_t)NTOK * EDIM]; // GEMM output [tok][3d], fp16
__device__ float  g_sumA[BATCH * NSEG * DIM];  // per-segment gate products
__device__ float  g_sumY[BATCH * NSEG * DIM];  // per-segment local scan tails
__device__ float  g_carry[BATCH * NSEG * DIM]; // exclusive carry entering each segment

// ===================== PTX helpers (all valid on compute_103) ==========
__device__ __forceinline__ uint32_t smem_u32(const void* p) {
    uint32_t r;
    asm("{ .reg .u64 t; cvta.to.shared.u64 t, %1; cvt.u32.u64 %0, t; }" : "=r"(r) : "l"(p));
    return r;
}
__device__ __forceinline__ void cp16(uint32_t dst, const void* src) {
    asm volatile("cp.async.cg.shared.global [%0], [%1], 16;" :: "r"(dst), "l"(src));
}
#define CP_COMMIT() asm volatile("cp.async.commit_group;" ::: "memory")
#define CP_WAIT2()  asm volatile("cp.async.wait_group 2;" ::: "memory")

__device__ __forceinline__ void ldm_x4(uint32_t* r, uint32_t addr) {
    asm volatile("ldmatrix.sync.aligned.m8n8.x4.shared.b16 {%0,%1,%2,%3}, [%4];"
                 : "=r"(r[0]), "=r"(r[1]), "=r"(r[2]), "=r"(r[3]) : "r"(addr));
}
__device__ __forceinline__ void mma16816(float* c, const uint32_t* a, const uint32_t* b) {
    asm volatile(
        "mma.sync.aligned.m16n8k16.row.col.f32.f16.f16.f32 "
        "{%0,%1,%2,%3}, {%4,%5,%6,%7}, {%8,%9}, {%0,%1,%2,%3};"
        : "+f"(c[0]), "+f"(c[1]), "+f"(c[2]), "+f"(c[3])
        : "r"(a[0]), "r"(a[1]), "r"(a[2]), "r"(a[3]), "r"(b[0]), "r"(b[1]));
}

// ===================== kernel 1: RMSNorm -> fp16 activations ==============
__global__ void rmsnorm_kernel(const float* __restrict__ x, const float* __restrict__ gamma) {
    __shared__ float red[8];
    const int tok = blockIdx.x;
    const int tid = threadIdx.x;   // 256 threads, 4 elems each
    float4 v = ((const float4*)(x + (size_t)tok * DIM))[tid];
    float s = v.x * v.x + v.y * v.y + v.z * v.z + v.w * v.w;
    #pragma unroll
    for (int o = 16; o; o >>= 1) s += __shfl_xor_sync(0xffffffffu, s, o);
    if ((tid & 31) == 0) red[tid >> 5] = s;
    __syncthreads();
    if (tid == 0) {
        float t = 0.f;
        #pragma unroll
        for (int i = 0; i < 8; i++) t += red[i];
        red[0] = 32.0f / fmaxf(sqrtf(t), 1e-12f);   // sqrt(DIM)=32
    }
    __syncthreads();
    const float scl = red[0];
    float4 g = ((const float4*)gamma)[tid];
    __half2* hh = (__half2*)(g_ha + (size_t)tok * DIM);
    hh[2 * tid]     = __floats2half2_rn(v.x * scl * g.x, v.y * scl * g.y);
    hh[2 * tid + 1] = __floats2half2_rn(v.z * scl * g.z, v.w * scl * g.w);
}

// ===================== kernel 2: weight convert -> fp16 ====================
__global__ void wconv_kernel(const float* __restrict__ w) {
    size_t i4 = (size_t)blockIdx.x * 256 + threadIdx.x;   // EDIM*DIM/4 float4s
    float4 v = ((const float4*)w)[i4];
    ((__half2*)g_wh)[2 * i4]     = __floats2half2_rn(v.x, v.y);
    ((__half2*)g_wh)[2 * i4 + 1] = __floats2half2_rn(v.z, v.w);
}

// ===================== kernel 3: HMMA GEMM, CTA 128x128, 4 warps 64x64 =====
// qkva[m][e] = sum_d h[m][d]*w[e][d]; BK=32, 4-stage cp.async, 2 CTAs/SM,
// register-double-buffered fragments, fp16 output.
#define PITCHB 80
#define TILEB  (128 * PITCHB)          // 10240
#define OFF_A  0
#define OFF_B  TILEB
#define STAGEB (2 * TILEB)             // 20480
#define NSTAGE 4
#define NKC    32                      // 1024 / 32
#define GEMM_SMEM (NSTAGE * STAGEB)    // 81920 -> 2 CTAs/SM

__device__ __forceinline__ void load_stage(uint32_t sm_stage,
                                           const __half* A, const __half* B,
                                           int koff, int tid) {
    #pragma unroll
    for (int i = 0; i < 4; i++) {
        const int c   = tid + i * 128;       // 0..511
        const int row = c >> 2;
        const int kc4 = c & 3;
        const uint32_t so = (uint32_t)(row * PITCHB + kc4 * 16);
        const size_t   go = (size_t)row * DIM + koff + kc4 * 8;
        cp16(sm_stage + OFF_A + so, A + go);
        cp16(sm_stage + OFF_B + so, B + go);
    }
}

__device__ __forceinline__ void load_frags(uint32_t* ah, uint32_t* bf,
                                           uint32_t sb, uint32_t a_base, uint32_t b_base,
                                           int step) {
    #pragma unroll
    for (int mt = 0; mt < 4; mt++)
        ldm_x4(ah + 4 * mt, sb + OFF_A + a_base + step * 32 + mt * 16 * PITCHB);
    #pragma unroll
    for (int p = 0; p < 4; p++)
        ldm_x4(bf + 4 * p, sb + OFF_B + b_base + step * 32 + p * 16 * PITCHB);
}

__global__ void __launch_bounds__(128, 2) gemm_kernel() {
    extern __shared__ char smem[];
    const uint32_t smem_base = smem_u32(smem);
    const int tid  = threadIdx.x;
    const int wid  = tid >> 5;       // 0..3
    const int lane = tid & 31;
    const int warp_m = wid >> 1;     // 0..1 -> 64-row strip
    const int warp_n = wid & 1;      // 0..1 -> 64-col strip
    const int ntile = blockIdx.x;    // 0..23 (fast dim -> A tile hot in L2)
    const int mtile = blockIdx.y;    // 0..127

    const __half* A = g_ha + (size_t)(mtile * 128) * DIM;
    const __half* B = g_wh + (size_t)(ntile * 128) * DIM;

    #pragma unroll
    for (int s = 0; s < NSTAGE - 1; s++) {
        load_stage(smem_base + s * STAGEB, A, B, s * 32, tid);
        CP_COMMIT();
    }

    float acc[4][8][4];
    #pragma unroll
    for (int mt = 0; mt < 4; mt++)
        #pragma unroll
        for (int nt = 0; nt < 8; nt++)
            #pragma unroll
            for (int r = 0; r < 4; r++) acc[mt][nt][r] = 0.f;

    const uint32_t a_base = (uint32_t)((warp_m * 64 + (lane & 15)) * PITCHB) + ((lane >> 4) << 4);
    const uint32_t b_base = (uint32_t)((warp_n * 64 + ((lane >> 4) << 3) + (lane & 7)) * PITCHB)
                          + (((lane >> 3) & 1) << 4);

    uint32_t ah[2][16], bf[2][16];   // double-buffered per (kc,step)

    CP_WAIT2();
    __syncthreads();
    load_frags(ah[0], bf[0], smem_base, a_base, b_base, 0);

    for (int kc = 0; kc < NKC; kc++) {
        const uint32_t sb = smem_base + (kc & (NSTAGE - 1)) * STAGEB;
        if (kc + NSTAGE - 1 < NKC)
            load_stage(smem_base + ((kc + NSTAGE - 1) & (NSTAGE - 1)) * STAGEB,
                       A, B, (kc + NSTAGE - 1) * 32, tid);
        CP_COMMIT();

        load_frags(ah[1], bf[1], sb, a_base, b_base, 1);

        #pragma unroll
        for (int nt = 0; nt < 8; nt++)
            #pragma unroll
            for (int mt = 0; mt < 4; mt++)
                mma16816(acc[mt][nt], &ah[0][4 * mt], &bf[0][2 * nt]);

        if (kc + 1 < NKC) {
            CP_WAIT2();
            __syncthreads();
            const uint32_t sbn = smem_base + ((kc + 1) & (NSTAGE - 1)) * STAGEB;
            load_frags(ah[0], bf[0], sbn, a_base, b_base, 0);
        }

        #pragma unroll
        for (int nt = 0; nt < 8; nt++)
            #pragma unroll
            for (int mt = 0; mt < 4; mt++)
                mma16816(acc[mt][nt], &ah[1][4 * mt], &bf[1][2 * nt]);
    }

    // fp16 epilogue
    const int gid = lane >> 2, qid = lane & 3;
    #pragma unroll
    for (int mt = 0; mt < 4; mt++) {
        const int row0 = mtile * 128 + warp_m * 64 + mt * 16 + gid;
        #pragma unroll
        for (int nt = 0; nt < 8; nt++) {
            const int col = ntile * 128 + warp_n * 64 + nt * 8 + qid * 2;
            *(__half2*)(g_qkva + (size_t)row0 * EDIM + col) =
                __floats2half2_rn(acc[mt][nt][0], acc[mt][nt][1]);
            *(__half2*)(g_qkva + (size_t)(row0 + 8) * EDIM + col) =
                __floats2half2_rn(acc[mt][nt][2], acc[mt][nt][3]);
        }
    }
}

// ===================== kernel 4: scan pass A (local segment summaries) =====
// 2 channels/thread via half2. grid (DIM/512, NSEG, BATCH) = 1024 blocks.
__global__ void __launch_bounds__(256) scanA_kernel() {
    const int tid = threadIdx.x;
    const int d0  = blockIdx.x * 512 + tid * 2;
    const int seg = blockIdx.y;
    const int b   = blockIdx.z;
    const size_t tok0 = (size_t)b * SEQ + (size_t)seg * SEGL;
    const __half* base_kv = g_qkva + tok0 * EDIM + DIM + d0;
    const __half* base_av = g_qkva + tok0 * EDIM + 2 * DIM + d0;
    float pa0 = 1.f, pa1 = 1.f, y0 = 0.f, y1 = 0.f;
    #pragma unroll 8
    for (int i = 0; i < SEGL; i++) {
        const float2 kv = __half22float2(*(const __half2*)(base_kv + (size_t)i * EDIM));
        const float2 av = __half22float2(*(const __half2*)(base_av + (size_t)i * EDIM));
        const float a0 = 1.0f / (1.0f + __expf(-av.x));
        const float a1 = 1.0f / (1.0f + __expf(-av.y));
        y0 = a0 * y0 + kv.x;  pa0 *= a0;
        y1 = a1 * y1 + kv.y;  pa1 *= a1;
    }
    const size_t sidx = (size_t)(b * NSEG + seg) * DIM + d0;
    *(float2*)&g_sumA[sidx] = make_float2(pa0, pa1);
    *(float2*)&g_sumY[sidx] = make_float2(y0, y1);
}

// ===================== kernel 5: scan pass B (summary scan) ================
__global__ void __launch_bounds__(256) scanB_kernel() {
    const int idx = blockIdx.x * 256 + threadIdx.x;   // 0..4095
    const int b = idx >> 10;
    const int d = idx & (DIM - 1);
    float c = 0.f;
    #pragma unroll 8
    for (int s = 0; s < NSEG; s++) {
        const size_t i = (size_t)(b * NSEG + s) * DIM + d;
        g_carry[i] = c;                       // exclusive carry entering segment s
        c = g_sumA[i] * c + g_sumY[i];
    }
}

// ===================== kernel 6: scan pass C (recompute + q*y) =============
__global__ void __launch_bounds__(256) scanC_kernel(float* __restrict__ out) {
    const int tid = threadIdx.x;
    const int d0  = blockIdx.x * 512 + tid * 2;
    const int seg = blockIdx.y;
    const int b   = blockIdx.z;
    const size_t tok0 = (size_t)b * SEQ + (size_t)seg * SEGL;
    const __half* base_q  = g_qkva + tok0 * EDIM + d0;
    const __half* base_kv = g_qkva + tok0 * EDIM + DIM + d0;
    const __half* base_av = g_qkva + tok0 * EDIM + 2 * DIM + d0;
    float* outp = out + tok0 * DIM + d0;
    const float2 cin = *(const float2*)&g_carry[(size_t)(b * NSEG + seg) * DIM + d0];
    float y0 = cin.x, y1 = cin.y;
    #pragma unroll 8
    for (int i = 0; i < SEGL; i++) {
        const float2 kv = __half22float2(*(const __half2*)(base_kv + (size_t)i * EDIM));
        const float2 av = __half22float2(*(const __half2*)(base_av + (size_t)i * EDIM));
        const float2 q  = __half22float2(*(const __half2*)(base_q  + (size_t)i * EDIM));
        const float a0 = 1.0f / (1.0f + __expf(-av.x));
        const float a1 = 1.0f / (1.0f + __expf(-av.y));
        y0 = a0 * y0 + kv.x;
        y1 = a1 * y1 + kv.y;
        *(float2*)(outp + (size_t)i * DIM) = make_float2(q.x * y0, q.y * y1);
    }
}

// ===================== launcher =====================
extern "C" void kernel_launch(void* const* d_in, const int* in_sizes, int n_in,
                              void* d_out, int out_size) {
    const float* x     = (const float*)d_in[0];   // [4,4096,1024] f32
    const float* w     = (const float*)d_in[1];   // [3072,1024]  f32
    const float* gamma = (const float*)d_in[2];   // [1024]       f32
    float* out = (float*)d_out;

    cudaFuncSetAttribute(gemm_kernel, cudaFuncAttributeMaxDynamicSharedMemorySize, GEMM_SMEM);

    rmsnorm_kernel<<<NTOK, 256>>>(x, gamma);
    wconv_kernel<<<(EDIM * DIM / 4) / 256, 256>>>(w);
    gemm_kernel<<<dim3(EDIM / 128, NTOK / 128), 128, GEMM_SMEM>>>();
    scanA_kernel<<<dim3(DIM / 512, NSEG, BATCH), 256>>>();
    scanB_kernel<<<BATCH * DIM / 256, 256>>>();
    scanC_kernel<<<dim3(DIM / 512, NSEG, BATCH), 256>>>(out);
}

// round 13
// speedup vs baseline: 1.2831x; 1.0581x over previous
#include <cuda_runtime.h>
#include <cuda_fp16.h>
#include <cstdint>

// ===================== problem constants =====================
#define NTOK  16384          // B*N tokens
#define DIM   1024
#define EDIM  3072           // 3*DIM
#define BATCH 4
#define SEQ   4096
#define NSEG  128
#define SEGL  32             // SEQ / NSEG

// ===================== device scratch (no cudaMalloc allowed) ==========
__device__ __half g_ha[(size_t)NTOK * DIM];    // fp16 activations
__device__ __half g_wh[(size_t)EDIM * DIM];    // fp16 weights
__device__ __half g_qkva[(size_t)NTOK * EDIM]; // GEMM output [tok][3d], fp16
__device__ float  g_sumA[BATCH * NSEG * DIM];  // per-segment gate products
__device__ float  g_sumY[BATCH * NSEG * DIM];  // per-segment local scan tails
__device__ float  g_carry[BATCH * NSEG * DIM]; // exclusive carry entering each segment

// ===================== PTX helpers (all valid on compute_103) ==========
__device__ __forceinline__ uint32_t smem_u32(const void* p) {
    uint32_t r;
    asm("{ .reg .u64 t; cvta.to.shared.u64 t, %1; cvt.u32.u64 %0, t; }" : "=r"(r) : "l"(p));
    return r;
}
__device__ __forceinline__ void cp16(uint32_t dst, const void* src) {
    asm volatile("cp.async.cg.shared.global [%0], [%1], 16;" :: "r"(dst), "l"(src));
}
#define CP_COMMIT() asm volatile("cp.async.commit_group;" ::: "memory")
#define CP_WAIT1()  asm volatile("cp.async.wait_group 1;" ::: "memory")

__device__ __forceinline__ void ldm_x4(uint32_t* r, uint32_t addr) {
    asm volatile("ldmatrix.sync.aligned.m8n8.x4.shared.b16 {%0,%1,%2,%3}, [%4];"
                 : "=r"(r[0]), "=r"(r[1]), "=r"(r[2]), "=r"(r[3]) : "r"(addr));
}
__device__ __forceinline__ void mma16816(float* c, const uint32_t* a, const uint32_t* b) {
    asm volatile(
        "mma.sync.aligned.m16n8k16.row.col.f32.f16.f16.f32 "
        "{%0,%1,%2,%3}, {%4,%5,%6,%7}, {%8,%9}, {%0,%1,%2,%3};"
        : "+f"(c[0]), "+f"(c[1]), "+f"(c[2]), "+f"(c[3])
        : "r"(a[0]), "r"(a[1]), "r"(a[2]), "r"(a[3]), "r"(b[0]), "r"(b[1]));
}

// ===================== kernel 1: fused prep (RMSNorm | weight convert) =====
// blocks [0, NTOK): rmsnorm of one token; blocks [NTOK, NTOK+3072): wconv chunk.
__global__ void prep_kernel(const float* __restrict__ x, const float* __restrict__ w,
                            const float* __restrict__ gamma) {
    const int tid = threadIdx.x;
    if (blockIdx.x < NTOK) {
        __shared__ float red[8];
        const int tok = blockIdx.x;
        float4 v = ((const float4*)(x + (size_t)tok * DIM))[tid];
        float s = v.x * v.x + v.y * v.y + v.z * v.z + v.w * v.w;
        #pragma unroll
        for (int o = 16; o; o >>= 1) s += __shfl_xor_sync(0xffffffffu, s, o);
        if ((tid & 31) == 0) red[tid >> 5] = s;
        __syncthreads();
        if (tid == 0) {
            float t = 0.f;
            #pragma unroll
            for (int i = 0; i < 8; i++) t += red[i];
            red[0] = 32.0f / fmaxf(sqrtf(t), 1e-12f);   // sqrt(DIM)=32
        }
        __syncthreads();
        const float scl = red[0];
        float4 g = ((const float4*)gamma)[tid];
        __half2* hh = (__half2*)(g_ha + (size_t)tok * DIM);
        hh[2 * tid]     = __floats2half2_rn(v.x * scl * g.x, v.y * scl * g.y);
        hh[2 * tid + 1] = __floats2half2_rn(v.z * scl * g.z, v.w * scl * g.w);
    } else {
        const size_t i4 = (size_t)(blockIdx.x - NTOK) * 256 + tid;   // EDIM*DIM/4 float4s
        float4 v = ((const float4*)w)[i4];
        ((__half2*)g_wh)[2 * i4]     = __floats2half2_rn(v.x, v.y);
        ((__half2*)g_wh)[2 * i4 + 1] = __floats2half2_rn(v.z, v.w);
    }
}

// ===================== kernel 3: HMMA GEMM, CTA 128x128, 4 warps 64x64 =====
// BK=64, 3-stage cp.async ring, 2 CTAs/SM, register-double-buffered frags.
#define PITCHB 144                     // 64 fp16 = 128B + 16B pad
#define TILEB  (128 * PITCHB)          // 18432
#define OFF_A  0
#define OFF_B  TILEB
#define STAGEB (2 * TILEB)             // 36864
#define NSTAGE 3
#define NKC    16                      // 1024 / 64
#define GEMM_SMEM (NSTAGE * STAGEB)    // 110592 -> 2 CTAs/SM (216KB/SM)

__device__ __forceinline__ void load_stage(uint32_t sm_stage,
                                           const __half* A, const __half* B,
                                           int koff, int tid) {
    #pragma unroll
    for (int i = 0; i < 8; i++) {
        const int c   = tid + i * 128;       // 0..1023
        const int row = c >> 3;              // 0..127
        const int ch  = c & 7;               // eight 16B chunks per 128B row
        const uint32_t so = (uint32_t)(row * PITCHB + ch * 16);
        const size_t   go = (size_t)row * DIM + koff + ch * 8;
        cp16(sm_stage + OFF_A + so, A + go);
        cp16(sm_stage + OFF_B + so, B + go);
    }
}

// Load one (stage, step) worth of fragments: A 4x ldm_x4, B 4x ldm_x4.
__device__ __forceinline__ void load_frags(uint32_t* ah, uint32_t* bf,
                                           uint32_t sb, uint32_t a_base, uint32_t b_base,
                                           int step) {
    #pragma unroll
    for (int mt = 0; mt < 4; mt++)
        ldm_x4(ah + 4 * mt, sb + OFF_A + a_base + step * 32 + mt * 16 * PITCHB);
    #pragma unroll
    for (int p = 0; p < 4; p++)
        ldm_x4(bf + 4 * p, sb + OFF_B + b_base + step * 32 + p * 16 * PITCHB);
}

__global__ void __launch_bounds__(128, 2) gemm_kernel() {
    extern __shared__ char smem[];
    const uint32_t smem_base = smem_u32(smem);
    const int tid  = threadIdx.x;
    const int wid  = tid >> 5;       // 0..3
    const int lane = tid & 31;
    const int warp_m = wid >> 1;     // 0..1 -> 64-row strip
    const int warp_n = wid & 1;      // 0..1 -> 64-col strip
    const int ntile = blockIdx.x;    // 0..23 (fast dim -> A tile hot in L2)
    const int mtile = blockIdx.y;    // 0..127

    const __half* A = g_ha + (size_t)(mtile * 128) * DIM;
    const __half* B = g_wh + (size_t)(ntile * 128) * DIM;

    // prologue: stages 0,1
    load_stage(smem_base + 0 * STAGEB, A, B, 0, tid);
    CP_COMMIT();
    load_stage(smem_base + 1 * STAGEB, A, B, 64, tid);
    CP_COMMIT();

    float acc[4][8][4];
    #pragma unroll
    for (int mt = 0; mt < 4; mt++)
        #pragma unroll
        for (int nt = 0; nt < 8; nt++)
            #pragma unroll
            for (int r = 0; r < 4; r++) acc[mt][nt][r] = 0.f;

    const uint32_t a_base = (uint32_t)((warp_m * 64 + (lane & 15)) * PITCHB) + ((lane >> 4) << 4);
    const uint32_t b_base = (uint32_t)((warp_n * 64 + ((lane >> 4) << 3) + (lane & 7)) * PITCHB)
                          + (((lane >> 3) & 1) << 4);

    uint32_t ah[2][16], bf[2][16];   // double-buffered per micro-step

    CP_WAIT1();                       // stage 0 resident
    __syncthreads();
    load_frags(ah[0], bf[0], smem_base, a_base, b_base, 0);

    int ic = 0;                       // stage index of kc (mod 3)
    for (int kc = 0; kc < NKC; kc++) {
        const uint32_t sb = smem_base + ic * STAGEB;
        const int in = (ic + 1 == NSTAGE) ? 0 : ic + 1;       // stage of kc+1
        const int ir = (in + 1 == NSTAGE) ? 0 : in + 1;       // refill slot = kc+2

        if (kc + 2 < NKC)
            load_stage(smem_base + ir * STAGEB, A, B, (kc + 2) * 64, tid);
        CP_COMMIT();

        // steps 0..2: prefetch next step's frags, then MMA current
        #pragma unroll
        for (int step = 0; step < 3; step++) {
            const int cur = step & 1, nxt = cur ^ 1;
            load_frags(ah[nxt], bf[nxt], sb, a_base, b_base, step + 1);
            #pragma unroll
            for (int nt = 0; nt < 8; nt++)
                #pragma unroll
                for (int mt = 0; mt < 4; mt++)
                    mma16816(acc[mt][nt], &ah[cur][4 * mt], &bf[cur][2 * nt]);
        }
        // barrier for stage kc+1, prefetch (kc+1, step 0) into buf0
        if (kc + 1 < NKC) {
            CP_WAIT1();               // <=1 group pending -> stage kc+1 resident
            __syncthreads();
            load_frags(ah[0], bf[0], smem_base + in * STAGEB, a_base, b_base, 0);
        }
        // MMA for step 3 (lives in buf1)
        #pragma unroll
        for (int nt = 0; nt < 8; nt++)
            #pragma unroll
            for (int mt = 0; mt < 4; mt++)
                mma16816(acc[mt][nt], &ah[1][4 * mt], &bf[1][2 * nt]);

        ic = in;
    }

    // fp16 epilogue
    const int gid = lane >> 2, qid = lane & 3;
    #pragma unroll
    for (int mt = 0; mt < 4; mt++) {
        const int row0 = mtile * 128 + warp_m * 64 + mt * 16 + gid;
        #pragma unroll
        for (int nt = 0; nt < 8; nt++) {
            const int col = ntile * 128 + warp_n * 64 + nt * 8 + qid * 2;
            *(__half2*)(g_qkva + (size_t)row0 * EDIM + col) =
                __floats2half2_rn(acc[mt][nt][0], acc[mt][nt][1]);
            *(__half2*)(g_qkva + (size_t)(row0 + 8) * EDIM + col) =
                __floats2half2_rn(acc[mt][nt][2], acc[mt][nt][3]);
        }
    }
}

// ===================== kernel 4: scan pass A (local segment summaries) =====
// 2 channels/thread via half2. grid (DIM/512, NSEG, BATCH) = 1024 blocks.
__global__ void __launch_bounds__(256) scanA_kernel() {
    const int tid = threadIdx.x;
    const int d0  = blockIdx.x * 512 + tid * 2;
    const int seg = blockIdx.y;
    const int b   = blockIdx.z;
    const size_t tok0 = (size_t)b * SEQ + (size_t)seg * SEGL;
    const __half* base_kv = g_qkva + tok0 * EDIM + DIM + d0;
    const __half* base_av = g_qkva + tok0 * EDIM + 2 * DIM + d0;
    float pa0 = 1.f, pa1 = 1.f, y0 = 0.f, y1 = 0.f;
    #pragma unroll 8
    for (int i = 0; i < SEGL; i++) {
        const float2 kv = __half22float2(*(const __half2*)(base_kv + (size_t)i * EDIM));
        const float2 av = __half22float2(*(const __half2*)(base_av + (size_t)i * EDIM));
        const float a0 = 1.0f / (1.0f + __expf(-av.x));
        const float a1 = 1.0f / (1.0f + __expf(-av.y));
        y0 = a0 * y0 + kv.x;  pa0 *= a0;
        y1 = a1 * y1 + kv.y;  pa1 *= a1;
    }
    const size_t sidx = (size_t)(b * NSEG + seg) * DIM + d0;
    *(float2*)&g_sumA[sidx] = make_float2(pa0, pa1);
    *(float2*)&g_sumY[sidx] = make_float2(y0, y1);
}

// ===================== kernel 5: scan pass B (summary scan) ================
__global__ void __launch_bounds__(256) scanB_kernel() {
    const int idx = blockIdx.x * 256 + threadIdx.x;   // 0..4095
    const int b = idx >> 10;
    const int d = idx & (DIM - 1);
    float c = 0.f;
    #pragma unroll 8
    for (int s = 0; s < NSEG; s++) {
        const size_t i = (size_t)(b * NSEG + s) * DIM + d;
        g_carry[i] = c;                       // exclusive carry entering segment s
        c = g_sumA[i] * c + g_sumY[i];
    }
}

// ===================== kernel 6: scan pass C (recompute + q*y) =============
__global__ void __launch_bounds__(256) scanC_kernel(float* __restrict__ out) {
    const int tid = threadIdx.x;
    const int d0  = blockIdx.x * 512 + tid * 2;
    const int seg = blockIdx.y;
    const int b   = blockIdx.z;
    const size_t tok0 = (size_t)b * SEQ + (size_t)seg * SEGL;
    const __half* base_q  = g_qkva + tok0 * EDIM + d0;
    const __half* base_kv = g_qkva + tok0 * EDIM + DIM + d0;
    const __half* base_av = g_qkva + tok0 * EDIM + 2 * DIM + d0;
    float* outp = out + tok0 * DIM + d0;
    const float2 cin = *(const float2*)&g_carry[(size_t)(b * NSEG + seg) * DIM + d0];
    float y0 = cin.x, y1 = cin.y;
    #pragma unroll 8
    for (int i = 0; i < SEGL; i++) {
        const float2 kv = __half22float2(*(const __half2*)(base_kv + (size_t)i * EDIM));
        const float2 av = __half22float2(*(const __half2*)(base_av + (size_t)i * EDIM));
        const float2 q  = __half22float2(*(const __half2*)(base_q  + (size_t)i * EDIM));
        const float a0 = 1.0f / (1.0f + __expf(-av.x));
        const float a1 = 1.0f / (1.0f + __expf(-av.y));
        y0 = a0 * y0 + kv.x;
        y1 = a1 * y1 + kv.y;
        *(float2*)(outp + (size_t)i * DIM) = make_float2(q.x * y0, q.y * y1);
    }
}

// ===================== launcher =====================
extern "C" void kernel_launch(void* const* d_in, const int* in_sizes, int n_in,
                              void* d_out, int out_size) {
    const float* x     = (const float*)d_in[0];   // [4,4096,1024] f32
    const float* w     = (const float*)d_in[1];   // [3072,1024]  f32
    const float* gamma = (const float*)d_in[2];   // [1024]       f32
    float* out = (float*)d_out;

    cudaFuncSetAttribute(gemm_kernel, cudaFuncAttributeMaxDynamicSharedMemorySize, GEMM_SMEM);

    prep_kernel<<<NTOK + (EDIM * DIM / 4) / 256, 256>>>(x, w, gamma);
    gemm_kernel<<<dim3(EDIM / 128, NTOK / 128), 128, GEMM_SMEM>>>();
    scanA_kernel<<<dim3(DIM / 512, NSEG, BATCH), 256>>>();
    scanB_kernel<<<BATCH * DIM / 256, 256>>>();
    scanC_kernel<<<dim3(DIM / 512, NSEG, BATCH), 256>>>(out);
}

// round 14
// speedup vs baseline: 1.3815x; 1.0767x over previous
#include <cuda_runtime.h>
#include <cuda_fp16.h>
#include <cstdint>

// ===================== problem constants =====================
#define NTOK  16384          // B*N tokens
#define DIM   1024
#define EDIM  3072           // 3*DIM
#define BATCH 4
#define SEQ   4096
#define NSEG  128
#define SEGL  32             // SEQ / NSEG

// ===================== device scratch (no cudaMalloc allowed) ==========
__device__ __half g_ha[(size_t)NTOK * DIM];    // fp16 activations
__device__ __half g_wh[(size_t)EDIM * DIM];    // fp16 weights
__device__ __half g_qkva[(size_t)NTOK * EDIM]; // GEMM output [tok][3d], fp16
__device__ float  g_sumA[BATCH * NSEG * DIM];  // per-segment gate products
__device__ float  g_sumY[BATCH * NSEG * DIM];  // per-segment local scan tails
__device__ float  g_carry[BATCH * NSEG * DIM]; // exclusive carry entering each segment

// ===================== PTX helpers (all valid on compute_103) ==========
__device__ __forceinline__ uint32_t smem_u32(const void* p) {
    uint32_t r;
    asm("{ .reg .u64 t; cvta.to.shared.u64 t, %1; cvt.u32.u64 %0, t; }" : "=r"(r) : "l"(p));
    return r;
}
__device__ __forceinline__ void cp16(uint32_t dst, const void* src) {
    asm volatile("cp.async.cg.shared.global [%0], [%1], 16;" :: "r"(dst), "l"(src));
}
#define CP_COMMIT() asm volatile("cp.async.commit_group;" ::: "memory")
#define CP_WAIT1()  asm volatile("cp.async.wait_group 1;" ::: "memory")

__device__ __forceinline__ void ldm_x4(uint32_t* r, uint32_t addr) {
    asm volatile("ldmatrix.sync.aligned.m8n8.x4.shared.b16 {%0,%1,%2,%3}, [%4];"
                 : "=r"(r[0]), "=r"(r[1]), "=r"(r[2]), "=r"(r[3]) : "r"(addr));
}
__device__ __forceinline__ void mma16816(float* c, const uint32_t* a, const uint32_t* b) {
    asm volatile(
        "mma.sync.aligned.m16n8k16.row.col.f32.f16.f16.f32 "
        "{%0,%1,%2,%3}, {%4,%5,%6,%7}, {%8,%9}, {%0,%1,%2,%3};"
        : "+f"(c[0]), "+f"(c[1]), "+f"(c[2]), "+f"(c[3])
        : "r"(a[0]), "r"(a[1]), "r"(a[2]), "r"(a[3]), "r"(b[0]), "r"(b[1]));
}

// ===================== kernel 1: fused prep (RMSNorm | weight convert) =====
__global__ void prep_kernel(const float* __restrict__ x, const float* __restrict__ w,
                            const float* __restrict__ gamma) {
    const int tid = threadIdx.x;
    if (blockIdx.x < NTOK) {
        __shared__ float red[8];
        const int tok = blockIdx.x;
        float4 v = ((const float4*)(x + (size_t)tok * DIM))[tid];
        float s = v.x * v.x + v.y * v.y + v.z * v.z + v.w * v.w;
        #pragma unroll
        for (int o = 16; o; o >>= 1) s += __shfl_xor_sync(0xffffffffu, s, o);
        if ((tid & 31) == 0) red[tid >> 5] = s;
        __syncthreads();
        if (tid == 0) {
            float t = 0.f;
            #pragma unroll
            for (int i = 0; i < 8; i++) t += red[i];
            red[0] = 32.0f / fmaxf(sqrtf(t), 1e-12f);   // sqrt(DIM)=32
        }
        __syncthreads();
        const float scl = red[0];
        float4 g = ((const float4*)gamma)[tid];
        __half2* hh = (__half2*)(g_ha + (size_t)tok * DIM);
        hh[2 * tid]     = __floats2half2_rn(v.x * scl * g.x, v.y * scl * g.y);
        hh[2 * tid + 1] = __floats2half2_rn(v.z * scl * g.z, v.w * scl * g.w);
    } else {
        const size_t i4 = (size_t)(blockIdx.x - NTOK) * 256 + tid;   // EDIM*DIM/4 float4s
        float4 v = ((const float4*)w)[i4];
        ((__half2*)g_wh)[2 * i4]     = __floats2half2_rn(v.x, v.y);
        ((__half2*)g_wh)[2 * i4 + 1] = __floats2half2_rn(v.z, v.w);
    }
}

// ===================== kernel 3: HMMA GEMM, CTA 128x128, 4 warps 64x64 =====
// BK=64, 3-stage cp.async ring, 2 CTAs/SM, register-double-buffered frags.
#define PITCHB 144                     // 64 fp16 = 128B + 16B pad
#define TILEB  (128 * PITCHB)          // 18432
#define OFF_A  0
#define OFF_B  TILEB
#define STAGEB (2 * TILEB)             // 36864
#define NSTAGE 3
#define NKC    16                      // 1024 / 64
#define GEMM_SMEM (NSTAGE * STAGEB)    // 110592 -> 2 CTAs/SM (216KB/SM)

__device__ __forceinline__ void load_stage(uint32_t sm_stage,
                                           const __half* A, const __half* B,
                                           int koff, int tid) {
    #pragma unroll
    for (int i = 0; i < 8; i++) {
        const int c   = tid + i * 128;       // 0..1023
        const int row = c >> 3;              // 0..127
        const int ch  = c & 7;               // eight 16B chunks per 128B row
        const uint32_t so = (uint32_t)(row * PITCHB + ch * 16);
        const size_t   go = (size_t)row * DIM + koff + ch * 8;
        cp16(sm_stage + OFF_A + so, A + go);
        cp16(sm_stage + OFF_B + so, B + go);
    }
}

__device__ __forceinline__ void load_frags(uint32_t* ah, uint32_t* bf,
                                           uint32_t sb, uint32_t a_base, uint32_t b_base,
                                           int step) {
    #pragma unroll
    for (int mt = 0; mt < 4; mt++)
        ldm_x4(ah + 4 * mt, sb + OFF_A + a_base + step * 32 + mt * 16 * PITCHB);
    #pragma unroll
    for (int p = 0; p < 4; p++)
        ldm_x4(bf + 4 * p, sb + OFF_B + b_base + step * 32 + p * 16 * PITCHB);
}

__global__ void __launch_bounds__(128, 2) gemm_kernel() {
    extern __shared__ char smem[];
    const uint32_t smem_base = smem_u32(smem);
    const int tid  = threadIdx.x;
    const int wid  = tid >> 5;       // 0..3
    const int lane = tid & 31;
    const int warp_m = wid >> 1;     // 0..1 -> 64-row strip
    const int warp_n = wid & 1;      // 0..1 -> 64-col strip
    const int ntile = blockIdx.x;    // 0..23 (fast dim -> A tile hot in L2)
    const int mtile = blockIdx.y;    // 0..127

    const __half* A = g_ha + (size_t)(mtile * 128) * DIM;
    const __half* B = g_wh + (size_t)(ntile * 128) * DIM;

    load_stage(smem_base + 0 * STAGEB, A, B, 0, tid);
    CP_COMMIT();
    load_stage(smem_base + 1 * STAGEB, A, B, 64, tid);
    CP_COMMIT();

    float acc[4][8][4];
    #pragma unroll
    for (int mt = 0; mt < 4; mt++)
        #pragma unroll
        for (int nt = 0; nt < 8; nt++)
            #pragma unroll
            for (int r = 0; r < 4; r++) acc[mt][nt][r] = 0.f;

    const uint32_t a_base = (uint32_t)((warp_m * 64 + (lane & 15)) * PITCHB) + ((lane >> 4) << 4);
    const uint32_t b_base = (uint32_t)((warp_n * 64 + ((lane >> 4) << 3) + (lane & 7)) * PITCHB)
                          + (((lane >> 3) & 1) << 4);

    uint32_t ah[2][16], bf[2][16];   // double-buffered per micro-step

    CP_WAIT1();                       // stage 0 resident
    __syncthreads();
    load_frags(ah[0], bf[0], smem_base, a_base, b_base, 0);

    int ic = 0;                       // stage index of kc (mod 3)
    for (int kc = 0; kc < NKC; kc++) {
        const uint32_t sb = smem_base + ic * STAGEB;
        const int in = (ic + 1 == NSTAGE) ? 0 : ic + 1;       // stage of kc+1
        const int ir = (in + 1 == NSTAGE) ? 0 : in + 1;       // refill slot = kc+2

        if (kc + 2 < NKC)
            load_stage(smem_base + ir * STAGEB, A, B, (kc + 2) * 64, tid);
        CP_COMMIT();

        #pragma unroll
        for (int step = 0; step < 3; step++) {
            const int cur = step & 1, nxt = cur ^ 1;
            load_frags(ah[nxt], bf[nxt], sb, a_base, b_base, step + 1);
            #pragma unroll
            for (int nt = 0; nt < 8; nt++)
                #pragma unroll
                for (int mt = 0; mt < 4; mt++)
                    mma16816(acc[mt][nt], &ah[cur][4 * mt], &bf[cur][2 * nt]);
        }
        if (kc + 1 < NKC) {
            CP_WAIT1();
            __syncthreads();
            load_frags(ah[0], bf[0], smem_base + in * STAGEB, a_base, b_base, 0);
        }
        #pragma unroll
        for (int nt = 0; nt < 8; nt++)
            #pragma unroll
            for (int mt = 0; mt < 4; mt++)
                mma16816(acc[mt][nt], &ah[1][4 * mt], &bf[1][2 * nt]);

        ic = in;
    }

    // fp16 epilogue
    const int gid = lane >> 2, qid = lane & 3;
    #pragma unroll
    for (int mt = 0; mt < 4; mt++) {
        const int row0 = mtile * 128 + warp_m * 64 + mt * 16 + gid;
        #pragma unroll
        for (int nt = 0; nt < 8; nt++) {
            const int col = ntile * 128 + warp_n * 64 + nt * 8 + qid * 2;
            *(__half2*)(g_qkva + (size_t)row0 * EDIM + col) =
                __floats2half2_rn(acc[mt][nt][0], acc[mt][nt][1]);
            *(__half2*)(g_qkva + (size_t)(row0 + 8) * EDIM + col) =
                __floats2half2_rn(acc[mt][nt][2], acc[mt][nt][3]);
        }
    }
}

// ===================== kernel 4: scan pass A (local segment summaries) =====
__global__ void __launch_bounds__(256) scanA_kernel() {
    const int tid = threadIdx.x;
    const int d0  = blockIdx.x * 512 + tid * 2;
    const int seg = blockIdx.y;
    const int b   = blockIdx.z;
    const size_t tok0 = (size_t)b * SEQ + (size_t)seg * SEGL;
    const __half* base_kv = g_qkva + tok0 * EDIM + DIM + d0;
    const __half* base_av = g_qkva + tok0 * EDIM + 2 * DIM + d0;
    float pa0 = 1.f, pa1 = 1.f, y0 = 0.f, y1 = 0.f;
    #pragma unroll 8
    for (int i = 0; i < SEGL; i++) {
        const float2 kv = __half22float2(*(const __half2*)(base_kv + (size_t)i * EDIM));
        const float2 av = __half22float2(*(const __half2*)(base_av + (size_t)i * EDIM));
        const float a0 = 1.0f / (1.0f + __expf(-av.x));
        const float a1 = 1.0f / (1.0f + __expf(-av.y));
        y0 = a0 * y0 + kv.x;  pa0 *= a0;
        y1 = a1 * y1 + kv.y;  pa1 *= a1;
    }
    const size_t sidx = (size_t)(b * NSEG + seg) * DIM + d0;
    *(float2*)&g_sumA[sidx] = make_float2(pa0, pa1);
    *(float2*)&g_sumY[sidx] = make_float2(y0, y1);
}

// ===================== kernel 5: scan pass B — Kogge-Stone parallel scan ===
// One block per (2 dims, batch); thread = segment. Operator:
// combine((Ap,Yp),(a,y)) = (a*Ap, a*Yp + y). All loads issue in parallel.
__global__ void __launch_bounds__(256) scanB_kernel() {
    const int tid  = threadIdx.x;
    const int col  = tid >> 7;           // 0..1
    const int s    = tid & 127;          // segment
    const int lane = s & 31;
    const int wc   = s >> 5;             // warp index within column (0..3)
    const int d    = blockIdx.x * 2 + col;
    const int b    = blockIdx.y;
    const size_t idx = (size_t)(b * NSEG + s) * DIM + d;

    float a = g_sumA[idx];
    float y = g_sumY[idx];

    // intra-warp inclusive scan (segments s-31..s within warp)
    #pragma unroll
    for (int off = 1; off < 32; off <<= 1) {
        const float ap = __shfl_up_sync(0xffffffffu, a, off);
        const float yp = __shfl_up_sync(0xffffffffu, y, off);
        if (lane >= off) { y = a * yp + y; a = a * ap; }
    }

    // cross-warp fixup
    __shared__ float sA[2][4], sY[2][4], sI[2][128];
    if (lane == 31) { sA[col][wc] = a; sY[col][wc] = y; }
    __syncthreads();
    float Ap = 1.f, Yp = 0.f;
    for (int ww = 0; ww < wc; ww++) {
        const float Aw = sA[col][ww], Yw = sY[col][ww];
        Yp = Aw * Yp + Yw;
        Ap = Aw * Ap;
    }
    y = a * Yp + y;   // global inclusive value for segment s

    // exclusive carry: value of segment s-1
    sI[col][s] = y;
    __syncthreads();
    g_carry[idx] = (s == 0) ? 0.f : sI[col][s - 1];
}

// ===================== kernel 6: scan pass C (recompute + q*y) =============
__global__ void __launch_bounds__(256) scanC_kernel(float* __restrict__ out) {
    const int tid = threadIdx.x;
    const int d0  = blockIdx.x * 512 + tid * 2;
    const int seg = blockIdx.y;
    const int b   = blockIdx.z;
    const size_t tok0 = (size_t)b * SEQ + (size_t)seg * SEGL;
    const __half* base_q  = g_qkva + tok0 * EDIM + d0;
    const __half* base_kv = g_qkva + tok0 * EDIM + DIM + d0;
    const __half* base_av = g_qkva + tok0 * EDIM + 2 * DIM + d0;
    float* outp = out + tok0 * DIM + d0;
    const float2 cin = *(const float2*)&g_carry[(size_t)(b * NSEG + seg) * DIM + d0];
    float y0 = cin.x, y1 = cin.y;
    #pragma unroll 8
    for (int i = 0; i < SEGL; i++) {
        const float2 kv = __half22float2(*(const __half2*)(base_kv + (size_t)i * EDIM));
        const float2 av = __half22float2(*(const __half2*)(base_av + (size_t)i * EDIM));
        const float2 q  = __half22float2(*(const __half2*)(base_q  + (size_t)i * EDIM));
        const float a0 = 1.0f / (1.0f + __expf(-av.x));
        const float a1 = 1.0f / (1.0f + __expf(-av.y));
        y0 = a0 * y0 + kv.x;
        y1 = a1 * y1 + kv.y;
        *(float2*)(outp + (size_t)i * DIM) = make_float2(q.x * y0, q.y * y1);
    }
}

// ===================== launcher =====================
extern "C" void kernel_launch(void* const* d_in, const int* in_sizes, int n_in,
                              void* d_out, int out_size) {
    const float* x     = (const float*)d_in[0];   // [4,4096,1024] f32
    const float* w     = (const float*)d_in[1];   // [3072,1024]  f32
    const float* gamma = (const float*)d_in[2];   // [1024]       f32
    float* out = (float*)d_out;

    cudaFuncSetAttribute(gemm_kernel, cudaFuncAttributeMaxDynamicSharedMemorySize, GEMM_SMEM);

    prep_kernel<<<NTOK + (EDIM * DIM / 4) / 256, 256>>>(x, w, gamma);
    gemm_kernel<<<dim3(EDIM / 128, NTOK / 128), 128, GEMM_SMEM>>>();
    scanA_kernel<<<dim3(DIM / 512, NSEG, BATCH), 256>>>();
    scanB_kernel<<<dim3(DIM / 2, BATCH), 256>>>();
    scanC_kernel<<<dim3(DIM / 512, NSEG, BATCH), 256>>>(out);
}

// round 15
// speedup vs baseline: 1.4080x; 1.0192x over previous
#include <cuda_runtime.h>
#include <cuda_fp16.h>
#include <cstdint>

// ===================== problem constants =====================
#define NTOK  16384          // B*N tokens
#define DIM   1024
#define EDIM  3072           // 3*DIM
#define BATCH 4
#define SEQ   4096
#define NSEG  128
#define SEGL  32             // SEQ / NSEG

// ===================== device scratch (no cudaMalloc allowed) ==========
__device__ __half g_ha[(size_t)NTOK * DIM];    // fp16 activations
__device__ __half g_wh[(size_t)EDIM * DIM];    // fp16 weights
__device__ __half g_qkva[(size_t)NTOK * EDIM]; // GEMM output [tok][3d], fp16
__device__ float  g_sumA[BATCH * NSEG * DIM];  // per-segment gate products
__device__ float  g_sumY[BATCH * NSEG * DIM];  // per-segment local scan tails
__device__ float  g_carry[BATCH * NSEG * DIM]; // exclusive carry entering each segment

// ===================== PTX helpers (all valid on compute_103) ==========
__device__ __forceinline__ uint32_t smem_u32(const void* p) {
    uint32_t r;
    asm("{ .reg .u64 t; cvta.to.shared.u64 t, %1; cvt.u32.u64 %0, t; }" : "=r"(r) : "l"(p));
    return r;
}
__device__ __forceinline__ void cp16(uint32_t dst, const void* src) {
    asm volatile("cp.async.cg.shared.global [%0], [%1], 16;" :: "r"(dst), "l"(src));
}
#define CP_COMMIT() asm volatile("cp.async.commit_group;" ::: "memory")
#define CP_WAIT1()  asm volatile("cp.async.wait_group 1;" ::: "memory")

__device__ __forceinline__ void ldm_x4(uint32_t* r, uint32_t addr) {
    asm volatile("ldmatrix.sync.aligned.m8n8.x4.shared.b16 {%0,%1,%2,%3}, [%4];"
                 : "=r"(r[0]), "=r"(r[1]), "=r"(r[2]), "=r"(r[3]) : "r"(addr));
}
__device__ __forceinline__ void mma16816(float* c, const uint32_t* a, const uint32_t* b) {
    asm volatile(
        "mma.sync.aligned.m16n8k16.row.col.f32.f16.f16.f32 "
        "{%0,%1,%2,%3}, {%4,%5,%6,%7}, {%8,%9}, {%0,%1,%2,%3};"
        : "+f"(c[0]), "+f"(c[1]), "+f"(c[2]), "+f"(c[3])
        : "r"(a[0]), "r"(a[1]), "r"(a[2]), "r"(a[3]), "r"(b[0]), "r"(b[1]));
}

// ===================== kernel 1: fused prep (RMSNorm | weight convert) =====
__global__ void prep_kernel(const float* __restrict__ x, const float* __restrict__ w,
                            const float* __restrict__ gamma) {
    const int tid = threadIdx.x;
    if (blockIdx.x < NTOK) {
        __shared__ float red[8];
        const int tok = blockIdx.x;
        float4 v = ((const float4*)(x + (size_t)tok * DIM))[tid];
        float s = v.x * v.x + v.y * v.y + v.z * v.z + v.w * v.w;
        #pragma unroll
        for (int o = 16; o; o >>= 1) s += __shfl_xor_sync(0xffffffffu, s, o);
        if ((tid & 31) == 0) red[tid >> 5] = s;
        __syncthreads();
        if (tid == 0) {
            float t = 0.f;
            #pragma unroll
            for (int i = 0; i < 8; i++) t += red[i];
            red[0] = 32.0f / fmaxf(sqrtf(t), 1e-12f);   // sqrt(DIM)=32
        }
        __syncthreads();
        const float scl = red[0];
        float4 g = ((const float4*)gamma)[tid];
        __half2* hh = (__half2*)(g_ha + (size_t)tok * DIM);
        hh[2 * tid]     = __floats2half2_rn(v.x * scl * g.x, v.y * scl * g.y);
        hh[2 * tid + 1] = __floats2half2_rn(v.z * scl * g.z, v.w * scl * g.w);
    } else {
        const size_t i4 = (size_t)(blockIdx.x - NTOK) * 256 + tid;   // EDIM*DIM/4 float4s
        float4 v = ((const float4*)w)[i4];
        ((__half2*)g_wh)[2 * i4]     = __floats2half2_rn(v.x, v.y);
        ((__half2*)g_wh)[2 * i4 + 1] = __floats2half2_rn(v.z, v.w);
    }
}

// ===================== kernel 3: HMMA GEMM, CTA 128x128, 4 warps 64x64 =====
// BK=64, 3-stage cp.async ring, 2 CTAs/SM, register-double-buffered frags,
// smem-staged fully-coalesced fp16 epilogue.
#define PITCHB 144                     // 64 fp16 = 128B + 16B pad
#define TILEB  (128 * PITCHB)          // 18432
#define OFF_A  0
#define OFF_B  TILEB
#define STAGEB (2 * TILEB)             // 36864
#define NSTAGE 3
#define NKC    16                      // 1024 / 64
#define GEMM_SMEM (NSTAGE * STAGEB)    // 110592 -> 2 CTAs/SM (216KB/SM)
#define EPITCH 272                     // epilogue smem pitch: 256B data + 16B pad

__device__ __forceinline__ void load_stage(uint32_t sm_stage,
                                           const __half* A, const __half* B,
                                           int koff, int tid) {
    #pragma unroll
    for (int i = 0; i < 8; i++) {
        const int c   = tid + i * 128;       // 0..1023
        const int row = c >> 3;              // 0..127
        const int ch  = c & 7;               // eight 16B chunks per 128B row
        const uint32_t so = (uint32_t)(row * PITCHB + ch * 16);
        const size_t   go = (size_t)row * DIM + koff + ch * 8;
        cp16(sm_stage + OFF_A + so, A + go);
        cp16(sm_stage + OFF_B + so, B + go);
    }
}

__device__ __forceinline__ void load_frags(uint32_t* ah, uint32_t* bf,
                                           uint32_t sb, uint32_t a_base, uint32_t b_base,
                                           int step) {
    #pragma unroll
    for (int mt = 0; mt < 4; mt++)
        ldm_x4(ah + 4 * mt, sb + OFF_A + a_base + step * 32 + mt * 16 * PITCHB);
    #pragma unroll
    for (int p = 0; p < 4; p++)
        ldm_x4(bf + 4 * p, sb + OFF_B + b_base + step * 32 + p * 16 * PITCHB);
}

__global__ void __launch_bounds__(128, 2) gemm_kernel() {
    extern __shared__ char smem[];
    const uint32_t smem_base = smem_u32(smem);
    const int tid  = threadIdx.x;
    const int wid  = tid >> 5;       // 0..3
    const int lane = tid & 31;
    const int warp_m = wid >> 1;     // 0..1 -> 64-row strip
    const int warp_n = wid & 1;      // 0..1 -> 64-col strip
    const int ntile = blockIdx.x;    // 0..23 (fast dim -> A tile hot in L2)
    const int mtile = blockIdx.y;    // 0..127

    const __half* A = g_ha + (size_t)(mtile * 128) * DIM;
    const __half* B = g_wh + (size_t)(ntile * 128) * DIM;

    load_stage(smem_base + 0 * STAGEB, A, B, 0, tid);
    CP_COMMIT();
    load_stage(smem_base + 1 * STAGEB, A, B, 64, tid);
    CP_COMMIT();

    float acc[4][8][4];
    #pragma unroll
    for (int mt = 0; mt < 4; mt++)
        #pragma unroll
        for (int nt = 0; nt < 8; nt++)
            #pragma unroll
            for (int r = 0; r < 4; r++) acc[mt][nt][r] = 0.f;

    const uint32_t a_base = (uint32_t)((warp_m * 64 + (lane & 15)) * PITCHB) + ((lane >> 4) << 4);
    const uint32_t b_base = (uint32_t)((warp_n * 64 + ((lane >> 4) << 3) + (lane & 7)) * PITCHB)
                          + (((lane >> 3) & 1) << 4);

    uint32_t ah[2][16], bf[2][16];   // double-buffered per micro-step

    CP_WAIT1();                       // stage 0 resident
    __syncthreads();
    load_frags(ah[0], bf[0], smem_base, a_base, b_base, 0);

    int ic = 0;                       // stage index of kc (mod 3)
    for (int kc = 0; kc < NKC; kc++) {
        const uint32_t sb = smem_base + ic * STAGEB;
        const int in = (ic + 1 == NSTAGE) ? 0 : ic + 1;       // stage of kc+1
        const int ir = (in + 1 == NSTAGE) ? 0 : in + 1;       // refill slot = kc+2

        if (kc + 2 < NKC)
            load_stage(smem_base + ir * STAGEB, A, B, (kc + 2) * 64, tid);
        CP_COMMIT();

        #pragma unroll
        for (int step = 0; step < 3; step++) {
            const int cur = step & 1, nxt = cur ^ 1;
            load_frags(ah[nxt], bf[nxt], sb, a_base, b_base, step + 1);
            #pragma unroll
            for (int nt = 0; nt < 8; nt++)
                #pragma unroll
                for (int mt = 0; mt < 4; mt++)
                    mma16816(acc[mt][nt], &ah[cur][4 * mt], &bf[cur][2 * nt]);
        }
        if (kc + 1 < NKC) {
            CP_WAIT1();
            __syncthreads();
            load_frags(ah[0], bf[0], smem_base + in * STAGEB, a_base, b_base, 0);
        }
        #pragma unroll
        for (int nt = 0; nt < 8; nt++)
            #pragma unroll
            for (int mt = 0; mt < 4; mt++)
                mma16816(acc[mt][nt], &ah[1][4 * mt], &bf[1][2 * nt]);

        ic = in;
    }

    // ---- epilogue: stage fp16 tile in smem, then fully-coalesced stores ----
    __syncthreads();   // all MMAs done; smem stages free for reuse
    const int gid = lane >> 2, qid = lane & 3;
    #pragma unroll
    for (int mt = 0; mt < 4; mt++) {
        const int r0 = warp_m * 64 + mt * 16 + gid;
        #pragma unroll
        for (int nt = 0; nt < 8; nt++) {
            const int c = warp_n * 64 + nt * 8 + qid * 2;
            *(__half2*)(smem + r0 * EPITCH + c * 2) =
                __floats2half2_rn(acc[mt][nt][0], acc[mt][nt][1]);
            *(__half2*)(smem + (r0 + 8) * EPITCH + c * 2) =
                __floats2half2_rn(acc[mt][nt][2], acc[mt][nt][3]);
        }
    }
    __syncthreads();
    // 128 rows x 256B, 16B per thread-chunk: 2048 uint4, 16 per thread
    #pragma unroll
    for (int i = 0; i < 16; i++) {
        const int idx = i * 128 + tid;       // 0..2047
        const int row = idx >> 4;
        const int ch  = idx & 15;
        const uint4 v = *(const uint4*)(smem + row * EPITCH + ch * 16);
        *(uint4*)(g_qkva + (size_t)(mtile * 128 + row) * EDIM + ntile * 128 + ch * 8) = v;
    }
}

// ===================== kernel 4: scan pass A (local segment summaries) =====
// 4 channels/thread via 2x half2 (uint2 loads). grid (NSEG, BATCH), 256 thr.
__global__ void __launch_bounds__(256) scanA_kernel() {
    const int tid = threadIdx.x;
    const int d0  = tid * 4;             // 0..1020
    const int seg = blockIdx.x;
    const int b   = blockIdx.y;
    const size_t tok0 = (size_t)b * SEQ + (size_t)seg * SEGL;
    const __half* base_kv = g_qkva + tok0 * EDIM + DIM + d0;
    const __half* base_av = g_qkva + tok0 * EDIM + 2 * DIM + d0;
    float pa0 = 1.f, pa1 = 1.f, pa2 = 1.f, pa3 = 1.f;
    float y0 = 0.f, y1 = 0.f, y2 = 0.f, y3 = 0.f;
    #pragma unroll 8
    for (int i = 0; i < SEGL; i++) {
        const uint2 kvr = *(const uint2*)(base_kv + (size_t)i * EDIM);
        const uint2 avr = *(const uint2*)(base_av + (size_t)i * EDIM);
        const float2 kv01 = __half22float2(*(const __half2*)&kvr.x);
        const float2 kv23 = __half22float2(*(const __half2*)&kvr.y);
        const float2 av01 = __half22float2(*(const __half2*)&avr.x);
        const float2 av23 = __half22float2(*(const __half2*)&avr.y);
        const float a0 = 1.0f / (1.0f + __expf(-av01.x));
        const float a1 = 1.0f / (1.0f + __expf(-av01.y));
        const float a2 = 1.0f / (1.0f + __expf(-av23.x));
        const float a3 = 1.0f / (1.0f + __expf(-av23.y));
        y0 = a0 * y0 + kv01.x;  pa0 *= a0;
        y1 = a1 * y1 + kv01.y;  pa1 *= a1;
        y2 = a2 * y2 + kv23.x;  pa2 *= a2;
        y3 = a3 * y3 + kv23.y;  pa3 *= a3;
    }
    const size_t sidx = (size_t)(b * NSEG + seg) * DIM + d0;
    *(float4*)&g_sumA[sidx] = make_float4(pa0, pa1, pa2, pa3);
    *(float4*)&g_sumY[sidx] = make_float4(y0, y1, y2, y3);
}

// ===================== kernel 5: scan pass B — Kogge-Stone parallel scan ===
__global__ void __launch_bounds__(256) scanB_kernel() {
    const int tid  = threadIdx.x;
    const int col  = tid >> 7;           // 0..1
    const int s    = tid & 127;          // segment
    const int lane = s & 31;
    const int wc   = s >> 5;             // warp index within column (0..3)
    const int d    = blockIdx.x * 2 + col;
    const int b    = blockIdx.y;
    const size_t idx = (size_t)(b * NSEG + s) * DIM + d;

    float a = g_sumA[idx];
    float y = g_sumY[idx];

    #pragma unroll
    for (int off = 1; off < 32; off <<= 1) {
        const float ap = __shfl_up_sync(0xffffffffu, a, off);
        const float yp = __shfl_up_sync(0xffffffffu, y, off);
        if (lane >= off) { y = a * yp + y; a = a * ap; }
    }

    __shared__ float sA[2][4], sY[2][4], sI[2][128];
    if (lane == 31) { sA[col][wc] = a; sY[col][wc] = y; }
    __syncthreads();
    float Yp = 0.f;
    for (int ww = 0; ww < wc; ww++) {
        Yp = sA[col][ww] * Yp + sY[col][ww];
    }
    y = a * Yp + y;   // global inclusive value for segment s

    sI[col][s] = y;
    __syncthreads();
    g_carry[idx] = (s == 0) ? 0.f : sI[col][s - 1];
}

// ===================== kernel 6: scan pass C (recompute + q*y) =============
// 4 channels/thread. grid (NSEG, BATCH), 256 threads.
__global__ void __launch_bounds__(256) scanC_kernel(float* __restrict__ out) {
    const int tid = threadIdx.x;
    const int d0  = tid * 4;
    const int seg = blockIdx.x;
    const int b   = blockIdx.y;
    const size_t tok0 = (size_t)b * SEQ + (size_t)seg * SEGL;
    const __half* base_q  = g_qkva + tok0 * EDIM + d0;
    const __half* base_kv = g_qkva + tok0 * EDIM + DIM + d0;
    const __half* base_av = g_qkva + tok0 * EDIM + 2 * DIM + d0;
    float* outp = out + tok0 * DIM + d0;
    const float4 cin = *(const float4*)&g_carry[(size_t)(b * NSEG + seg) * DIM + d0];
    float y0 = cin.x, y1 = cin.y, y2 = cin.z, y3 = cin.w;
    #pragma unroll 8
    for (int i = 0; i < SEGL; i++) {
        const uint2 kvr = *(const uint2*)(base_kv + (size_t)i * EDIM);
        const uint2 avr = *(const uint2*)(base_av + (size_t)i * EDIM);
        const uint2 qr  = *(const uint2*)(base_q  + (size_t)i * EDIM);
        const float2 kv01 = __half22float2(*(const __half2*)&kvr.x);
        const float2 kv23 = __half22float2(*(const __half2*)&kvr.y);
        const float2 av01 = __half22float2(*(const __half2*)&avr.x);
        const float2 av23 = __half22float2(*(const __half2*)&avr.y);
        const float2 q01  = __half22float2(*(const __half2*)&qr.x);
        const float2 q23  = __half22float2(*(const __half2*)&qr.y);
        const float a0 = 1.0f / (1.0f + __expf(-av01.x));
        const float a1 = 1.0f / (1.0f + __expf(-av01.y));
        const float a2 = 1.0f / (1.0f + __expf(-av23.x));
        const float a3 = 1.0f / (1.0f + __expf(-av23.y));
        y0 = a0 * y0 + kv01.x;
        y1 = a1 * y1 + kv01.y;
        y2 = a2 * y2 + kv23.x;
        y3 = a3 * y3 + kv23.y;
        *(float4*)(outp + (size_t)i * DIM) =
            make_float4(q01.x * y0, q01.y * y1, q23.x * y2, q23.y * y3);
    }
}

// ===================== launcher =====================
extern "C" void kernel_launch(void* const* d_in, const int* in_sizes, int n_in,
                              void* d_out, int out_size) {
    const float* x     = (const float*)d_in[0];   // [4,4096,1024] f32
    const float* w     = (const float*)d_in[1];   // [3072,1024]  f32
    const float* gamma = (const float*)d_in[2];   // [1024]       f32
    float* out = (float*)d_out;

    cudaFuncSetAttribute(gemm_kernel, cudaFuncAttributeMaxDynamicSharedMemorySize, GEMM_SMEM);

    prep_kernel<<<NTOK + (EDIM * DIM / 4) / 256, 256>>>(x, w, gamma);
    gemm_kernel<<<dim3(EDIM / 128, NTOK / 128), 128, GEMM_SMEM>>>();
    scanA_kernel<<<dim3(NSEG, BATCH), 256>>>();
    scanB_kernel<<<dim3(DIM / 2, BATCH), 256>>>();
    scanC_kernel<<<dim3(NSEG, BATCH), 256>>>(out);
}

// round 16
// speedup vs baseline: 1.4244x; 1.0117x over previous
#include <cuda_runtime.h>
#include <cuda_fp16.h>
#include <cstdint>

// ===================== problem constants =====================
#define NTOK  16384          // B*N tokens
#define DIM   1024
#define EDIM  3072           // 3*DIM
#define BATCH 4
#define SEQ   4096
#define NSEG  128
#define SEGL  32             // SEQ / NSEG

// ===================== device scratch (no cudaMalloc allowed) ==========
__device__ __half g_ha[(size_t)NTOK * DIM];    // fp16 activations
__device__ __half g_wh[(size_t)EDIM * DIM];    // fp16 weights
__device__ __half g_qkva[(size_t)NTOK * EDIM]; // GEMM output [tok][3d], fp16
__device__ float  g_sumA[BATCH * NSEG * DIM];  // per-segment gate products
__device__ float  g_sumY[BATCH * NSEG * DIM];  // per-segment local scan tails
__device__ float  g_carry[BATCH * NSEG * DIM]; // exclusive carry entering each segment

// ===================== PTX helpers (all valid on compute_103) ==========
__device__ __forceinline__ uint32_t smem_u32(const void* p) {
    uint32_t r;
    asm("{ .reg .u64 t; cvta.to.shared.u64 t, %1; cvt.u32.u64 %0, t; }" : "=r"(r) : "l"(p));
    return r;
}
__device__ __forceinline__ void cp16(uint32_t dst, const void* src) {
    asm volatile("cp.async.cg.shared.global [%0], [%1], 16;" :: "r"(dst), "l"(src));
}
#define CP_COMMIT() asm volatile("cp.async.commit_group;" ::: "memory")
#define CP_WAIT1()  asm volatile("cp.async.wait_group 1;" ::: "memory")

__device__ __forceinline__ void ldm_x4(uint32_t* r, uint32_t addr) {
    asm volatile("ldmatrix.sync.aligned.m8n8.x4.shared.b16 {%0,%1,%2,%3}, [%4];"
                 : "=r"(r[0]), "=r"(r[1]), "=r"(r[2]), "=r"(r[3]) : "r"(addr));
}
__device__ __forceinline__ void mma16816(float* c, const uint32_t* a, const uint32_t* b) {
    asm volatile(
        "mma.sync.aligned.m16n8k16.row.col.f32.f16.f16.f32 "
        "{%0,%1,%2,%3}, {%4,%5,%6,%7}, {%8,%9}, {%0,%1,%2,%3};"
        : "+f"(c[0]), "+f"(c[1]), "+f"(c[2]), "+f"(c[3])
        : "r"(a[0]), "r"(a[1]), "r"(a[2]), "r"(a[3]), "r"(b[0]), "r"(b[1]));
}

// ===================== kernel 1: fused prep (RMSNorm | weight convert) =====
// rmsnorm: 1 token per WARP (no block barriers). Blocks [0, NTOK/8) do 8
// tokens each; blocks [NTOK/8, NTOK/8 + 3072) convert weight chunks.
#define RMS_BLOCKS (NTOK / 8)
__global__ void prep_kernel(const float* __restrict__ x, const float* __restrict__ w,
                            const float* __restrict__ gamma) {
    const int tid = threadIdx.x;
    if (blockIdx.x < RMS_BLOCKS) {
        const int lane = tid & 31;
        const int tok  = blockIdx.x * 8 + (tid >> 5);
        const float4* xr = (const float4*)(x + (size_t)tok * DIM);
        float4 v[8];
        float s = 0.f;
        #pragma unroll
        for (int i = 0; i < 8; i++) {
            v[i] = xr[lane + 32 * i];
            s += v[i].x * v[i].x + v[i].y * v[i].y + v[i].z * v[i].z + v[i].w * v[i].w;
        }
        #pragma unroll
        for (int o = 16; o; o >>= 1) s += __shfl_xor_sync(0xffffffffu, s, o);
        const float scl = 32.0f / fmaxf(sqrtf(s), 1e-12f);   // sqrt(DIM)=32
        __half2* hh = (__half2*)(g_ha + (size_t)tok * DIM);
        #pragma unroll
        for (int i = 0; i < 8; i++) {
            const float4 g = ((const float4*)gamma)[lane + 32 * i];
            hh[2 * (lane + 32 * i)]     = __floats2half2_rn(v[i].x * scl * g.x, v[i].y * scl * g.y);
            hh[2 * (lane + 32 * i) + 1] = __floats2half2_rn(v[i].z * scl * g.z, v[i].w * scl * g.w);
        }
    } else {
        const size_t i4 = (size_t)(blockIdx.x - RMS_BLOCKS) * 256 + tid;   // EDIM*DIM/4 float4s
        float4 v = ((const float4*)w)[i4];
        ((__half2*)g_wh)[2 * i4]     = __floats2half2_rn(v.x, v.y);
        ((__half2*)g_wh)[2 * i4 + 1] = __floats2half2_rn(v.z, v.w);
    }
}

// ===================== kernel 3: HMMA GEMM, CTA 128x128, 4 warps 64x64 =====
// BK=64, 3-stage cp.async ring, 2 CTAs/SM, register-double-buffered frags,
// smem-staged fully-coalesced fp16 epilogue.
#define PITCHB 144                     // 64 fp16 = 128B + 16B pad
#define TILEB  (128 * PITCHB)          // 18432
#define OFF_A  0
#define OFF_B  TILEB
#define STAGEB (2 * TILEB)             // 36864
#define NSTAGE 3
#define NKC    16                      // 1024 / 64
#define GEMM_SMEM (NSTAGE * STAGEB)    // 110592 -> 2 CTAs/SM (216KB/SM)
#define EPITCH 272                     // epilogue smem pitch: 256B data + 16B pad

__device__ __forceinline__ void load_stage(uint32_t sm_stage,
                                           const __half* A, const __half* B,
                                           int koff, int tid) {
    #pragma unroll
    for (int i = 0; i < 8; i++) {
        const int c   = tid + i * 128;       // 0..1023
        const int row = c >> 3;              // 0..127
        const int ch  = c & 7;               // eight 16B chunks per 128B row
        const uint32_t so = (uint32_t)(row * PITCHB + ch * 16);
        const size_t   go = (size_t)row * DIM + koff + ch * 8;
        cp16(sm_stage + OFF_A + so, A + go);
        cp16(sm_stage + OFF_B + so, B + go);
    }
}

__device__ __forceinline__ void load_frags(uint32_t* ah, uint32_t* bf,
                                           uint32_t sb, uint32_t a_base, uint32_t b_base,
                                           int step) {
    #pragma unroll
    for (int mt = 0; mt < 4; mt++)
        ldm_x4(ah + 4 * mt, sb + OFF_A + a_base + step * 32 + mt * 16 * PITCHB);
    #pragma unroll
    for (int p = 0; p < 4; p++)
        ldm_x4(bf + 4 * p, sb + OFF_B + b_base + step * 32 + p * 16 * PITCHB);
}

__global__ void __launch_bounds__(128, 2) gemm_kernel() {
    extern __shared__ char smem[];
    const uint32_t smem_base = smem_u32(smem);
    const int tid  = threadIdx.x;
    const int wid  = tid >> 5;       // 0..3
    const int lane = tid & 31;
    const int warp_m = wid >> 1;     // 0..1 -> 64-row strip
    const int warp_n = wid & 1;      // 0..1 -> 64-col strip
    const int ntile = blockIdx.x;    // 0..23 (fast dim -> A tile hot in L2)
    const int mtile = blockIdx.y;    // 0..127

    const __half* A = g_ha + (size_t)(mtile * 128) * DIM;
    const __half* B = g_wh + (size_t)(ntile * 128) * DIM;

    load_stage(smem_base + 0 * STAGEB, A, B, 0, tid);
    CP_COMMIT();
    load_stage(smem_base + 1 * STAGEB, A, B, 64, tid);
    CP_COMMIT();

    float acc[4][8][4];
    #pragma unroll
    for (int mt = 0; mt < 4; mt++)
        #pragma unroll
        for (int nt = 0; nt < 8; nt++)
            #pragma unroll
            for (int r = 0; r < 4; r++) acc[mt][nt][r] = 0.f;

    const uint32_t a_base = (uint32_t)((warp_m * 64 + (lane & 15)) * PITCHB) + ((lane >> 4) << 4);
    const uint32_t b_base = (uint32_t)((warp_n * 64 + ((lane >> 4) << 3) + (lane & 7)) * PITCHB)
                          + (((lane >> 3) & 1) << 4);

    uint32_t ah[2][16], bf[2][16];   // double-buffered per micro-step

    CP_WAIT1();                       // stage 0 resident
    __syncthreads();
    load_frags(ah[0], bf[0], smem_base, a_base, b_base, 0);

    int ic = 0;                       // stage index of kc (mod 3)
    for (int kc = 0; kc < NKC; kc++) {
        const uint32_t sb = smem_base + ic * STAGEB;
        const int in = (ic + 1 == NSTAGE) ? 0 : ic + 1;       // stage of kc+1
        const int ir = (in + 1 == NSTAGE) ? 0 : in + 1;       // refill slot = kc+2

        if (kc + 2 < NKC)
            load_stage(smem_base + ir * STAGEB, A, B, (kc + 2) * 64, tid);
        CP_COMMIT();

        #pragma unroll
        for (int step = 0; step < 3; step++) {
            const int cur = step & 1, nxt = cur ^ 1;
            load_frags(ah[nxt], bf[nxt], sb, a_base, b_base, step + 1);
            #pragma unroll
            for (int nt = 0; nt < 8; nt++)
                #pragma unroll
                for (int mt = 0; mt < 4; mt++)
                    mma16816(acc[mt][nt], &ah[cur][4 * mt], &bf[cur][2 * nt]);
        }
        if (kc + 1 < NKC) {
            CP_WAIT1();
            __syncthreads();
            load_frags(ah[0], bf[0], smem_base + in * STAGEB, a_base, b_base, 0);
        }
        #pragma unroll
        for (int nt = 0; nt < 8; nt++)
            #pragma unroll
            for (int mt = 0; mt < 4; mt++)
                mma16816(acc[mt][nt], &ah[1][4 * mt], &bf[1][2 * nt]);

        ic = in;
    }

    // ---- epilogue: stage fp16 tile in smem, then fully-coalesced stores ----
    __syncthreads();   // all MMAs done; smem stages free for reuse
    const int gid = lane >> 2, qid = lane & 3;
    #pragma unroll
    for (int mt = 0; mt < 4; mt++) {
        const int r0 = warp_m * 64 + mt * 16 + gid;
        #pragma unroll
        for (int nt = 0; nt < 8; nt++) {
            const int c = warp_n * 64 + nt * 8 + qid * 2;
            *(__half2*)(smem + r0 * EPITCH + c * 2) =
                __floats2half2_rn(acc[mt][nt][0], acc[mt][nt][1]);
            *(__half2*)(smem + (r0 + 8) * EPITCH + c * 2) =
                __floats2half2_rn(acc[mt][nt][2], acc[mt][nt][3]);
        }
    }
    __syncthreads();
    #pragma unroll
    for (int i = 0; i < 16; i++) {
        const int idx = i * 128 + tid;       // 0..2047
        const int row = idx >> 4;
        const int ch  = idx & 15;
        const uint4 v = *(const uint4*)(smem + row * EPITCH + ch * 16);
        *(uint4*)(g_qkva + (size_t)(mtile * 128 + row) * EDIM + ntile * 128 + ch * 8) = v;
    }
}

// ===================== kernel 4: scan pass A (local segment summaries) =====
__global__ void __launch_bounds__(256) scanA_kernel() {
    const int tid = threadIdx.x;
    const int d0  = tid * 4;             // 0..1020
    const int seg = blockIdx.x;
    const int b   = blockIdx.y;
    const size_t tok0 = (size_t)b * SEQ + (size_t)seg * SEGL;
    const __half* base_kv = g_qkva + tok0 * EDIM + DIM + d0;
    const __half* base_av = g_qkva + tok0 * EDIM + 2 * DIM + d0;
    float pa0 = 1.f, pa1 = 1.f, pa2 = 1.f, pa3 = 1.f;
    float y0 = 0.f, y1 = 0.f, y2 = 0.f, y3 = 0.f;
    #pragma unroll
    for (int i = 0; i < SEGL; i++) {
        const uint2 kvr = *(const uint2*)(base_kv + (size_t)i * EDIM);
        const uint2 avr = *(const uint2*)(base_av + (size_t)i * EDIM);
        const float2 kv01 = __half22float2(*(const __half2*)&kvr.x);
        const float2 kv23 = __half22float2(*(const __half2*)&kvr.y);
        const float2 av01 = __half22float2(*(const __half2*)&avr.x);
        const float2 av23 = __half22float2(*(const __half2*)&avr.y);
        const float a0 = 1.0f / (1.0f + __expf(-av01.x));
        const float a1 = 1.0f / (1.0f + __expf(-av01.y));
        const float a2 = 1.0f / (1.0f + __expf(-av23.x));
        const float a3 = 1.0f / (1.0f + __expf(-av23.y));
        y0 = a0 * y0 + kv01.x;  pa0 *= a0;
        y1 = a1 * y1 + kv01.y;  pa1 *= a1;
        y2 = a2 * y2 + kv23.x;  pa2 *= a2;
        y3 = a3 * y3 + kv23.y;  pa3 *= a3;
    }
    const size_t sidx = (size_t)(b * NSEG + seg) * DIM + d0;
    *(float4*)&g_sumA[sidx] = make_float4(pa0, pa1, pa2, pa3);
    *(float4*)&g_sumY[sidx] = make_float4(y0, y1, y2, y3);
}

// ===================== kernel 5: scan pass B — Kogge-Stone parallel scan ===
__global__ void __launch_bounds__(256) scanB_kernel() {
    const int tid  = threadIdx.x;
    const int col  = tid >> 7;           // 0..1
    const int s    = tid & 127;          // segment
    const int lane = s & 31;
    const int wc   = s >> 5;             // warp index within column (0..3)
    const int d    = blockIdx.x * 2 + col;
    const int b    = blockIdx.y;
    const size_t idx = (size_t)(b * NSEG + s) * DIM + d;

    float a = g_sumA[idx];
    float y = g_sumY[idx];

    #pragma unroll
    for (int off = 1; off < 32; off <<= 1) {
        const float ap = __shfl_up_sync(0xffffffffu, a, off);
        const float yp = __shfl_up_sync(0xffffffffu, y, off);
        if (lane >= off) { y = a * yp + y; a = a * ap; }
    }

    __shared__ float sA[2][4], sY[2][4], sI[2][128];
    if (lane == 31) { sA[col][wc] = a; sY[col][wc] = y; }
    __syncthreads();
    float Yp = 0.f;
    for (int ww = 0; ww < wc; ww++) {
        Yp = sA[col][ww] * Yp + sY[col][ww];
    }
    y = a * Yp + y;   // global inclusive value for segment s

    sI[col][s] = y;
    __syncthreads();
    g_carry[idx] = (s == 0) ? 0.f : sI[col][s - 1];
}

// ===================== kernel 6: scan pass C (recompute + q*y) =============
__global__ void __launch_bounds__(256) scanC_kernel(float* __restrict__ out) {
    const int tid = threadIdx.x;
    const int d0  = tid * 4;
    const int seg = blockIdx.x;
    const int b   = blockIdx.y;
    const size_t tok0 = (size_t)b * SEQ + (size_t)seg * SEGL;
    const __half* base_q  = g_qkva + tok0 * EDIM + d0;
    const __half* base_kv = g_qkva + tok0 * EDIM + DIM + d0;
    const __half* base_av = g_qkva + tok0 * EDIM + 2 * DIM + d0;
    float* outp = out + tok0 * DIM + d0;
    const float4 cin = *(const float4*)&g_carry[(size_t)(b * NSEG + seg) * DIM + d0];
    float y0 = cin.x, y1 = cin.y, y2 = cin.z, y3 = cin.w;
    #pragma unroll
    for (int i = 0; i < SEGL; i++) {
        const uint2 kvr = *(const uint2*)(base_kv + (size_t)i * EDIM);
        const uint2 avr = *(const uint2*)(base_av + (size_t)i * EDIM);
        const uint2 qr  = *(const uint2*)(base_q  + (size_t)i * EDIM);
        const float2 kv01 = __half22float2(*(const __half2*)&kvr.x);
        const float2 kv23 = __half22float2(*(const __half2*)&kvr.y);
        const float2 av01 = __half22float2(*(const __half2*)&avr.x);
        const float2 av23 = __half22float2(*(const __half2*)&avr.y);
        const float2 q01  = __half22float2(*(const __half2*)&qr.x);
        const float2 q23  = __half22float2(*(const __half2*)&qr.y);
        const float a0 = 1.0f / (1.0f + __expf(-av01.x));
        const float a1 = 1.0f / (1.0f + __expf(-av01.y));
        const float a2 = 1.0f / (1.0f + __expf(-av23.x));
        const float a3 = 1.0f / (1.0f + __expf(-av23.y));
        y0 = a0 * y0 + kv01.x;
        y1 = a1 * y1 + kv01.y;
        y2 = a2 * y2 + kv23.x;
        y3 = a3 * y3 + kv23.y;
        *(float4*)(outp + (size_t)i * DIM) =
            make_float4(q01.x * y0, q01.y * y1, q23.x * y2, q23.y * y3);
    }
}

// ===================== launcher =====================
extern "C" void kernel_launch(void* const* d_in, const int* in_sizes, int n_in,
                              void* d_out, int out_size) {
    const float* x     = (const float*)d_in[0];   // [4,4096,1024] f32
    const float* w     = (const float*)d_in[1];   // [3072,1024]  f32
    const float* gamma = (const float*)d_in[2];   // [1024]       f32
    float* out = (float*)d_out;

    cudaFuncSetAttribute(gemm_kernel, cudaFuncAttributeMaxDynamicSharedMemorySize, GEMM_SMEM);

    prep_kernel<<<RMS_BLOCKS + (EDIM * DIM / 4) / 256, 256>>>(x, w, gamma);
    gemm_kernel<<<dim3(EDIM / 128, NTOK / 128), 128, GEMM_SMEM>>>();
    scanA_kernel<<<dim3(NSEG, BATCH), 256>>>();
    scanB_kernel<<<dim3(DIM / 2, BATCH), 256>>>();
    scanC_kernel<<<dim3(NSEG, BATCH), 256>>>(out);
}

// round 17
// speedup vs baseline: 1.5000x; 1.0531x over previous
#include <cuda_runtime.h>
#include <cuda_fp16.h>
#include <cstdint>

// ===================== problem constants =====================
#define NTOK  16384          // B*N tokens
#define DIM   1024
#define EDIM  3072           // 3*DIM
#define BATCH 4
#define SEQ   4096
#define NSEG  128
#define SEGL  32             // SEQ / NSEG

// ===================== device scratch (no cudaMalloc allowed) ==========
__device__ __half g_ha[(size_t)NTOK * DIM];    // fp16 activations
__device__ __half g_wh[(size_t)EDIM * DIM];    // fp16 weights
__device__ __half g_qkva[(size_t)NTOK * EDIM]; // GEMM output [tok][3d], fp16
__device__ float  g_sumA[BATCH * NSEG * DIM];  // per-segment gate products
__device__ float  g_sumY[BATCH * NSEG * DIM];  // per-segment local scan tails
__device__ float  g_carry[BATCH * NSEG * DIM]; // exclusive carry entering each segment

// ===================== PTX helpers (all valid on compute_103) ==========
__device__ __forceinline__ uint32_t smem_u32(const void* p) {
    uint32_t r;
    asm("{ .reg .u64 t; cvta.to.shared.u64 t, %1; cvt.u32.u64 %0, t; }" : "=r"(r) : "l"(p));
    return r;
}
__device__ __forceinline__ void cp16(uint32_t dst, const void* src) {
    asm volatile("cp.async.cg.shared.global [%0], [%1], 16;" :: "r"(dst), "l"(src));
}
#define CP_COMMIT() asm volatile("cp.async.commit_group;" ::: "memory")
#define CP_WAIT1()  asm volatile("cp.async.wait_group 1;" ::: "memory")

__device__ __forceinline__ void ldm_x4(uint32_t* r, uint32_t addr) {
    asm volatile("ldmatrix.sync.aligned.m8n8.x4.shared.b16 {%0,%1,%2,%3}, [%4];"
                 : "=r"(r[0]), "=r"(r[1]), "=r"(r[2]), "=r"(r[3]) : "r"(addr));
}
__device__ __forceinline__ void mma16816(float* c, const uint32_t* a, const uint32_t* b) {
    asm volatile(
        "mma.sync.aligned.m16n8k16.row.col.f32.f16.f16.f32 "
        "{%0,%1,%2,%3}, {%4,%5,%6,%7}, {%8,%9}, {%0,%1,%2,%3};"
        : "+f"(c[0]), "+f"(c[1]), "+f"(c[2]), "+f"(c[3])
        : "r"(a[0]), "r"(a[1]), "r"(a[2]), "r"(a[3]), "r"(b[0]), "r"(b[1]));
}

// ===================== kernel 1: fused prep (RMSNorm | weight convert) =====
#define RMS_BLOCKS (NTOK / 8)
__global__ void prep_kernel(const float* __restrict__ x, const float* __restrict__ w,
                            const float* __restrict__ gamma) {
    const int tid = threadIdx.x;
    if (blockIdx.x < RMS_BLOCKS) {
        const int lane = tid & 31;
        const int tok  = blockIdx.x * 8 + (tid >> 5);
        const float4* xr = (const float4*)(x + (size_t)tok * DIM);
        float4 v[8];
        float s = 0.f;
        #pragma unroll
        for (int i = 0; i < 8; i++) {
            v[i] = xr[lane + 32 * i];
            s += v[i].x * v[i].x + v[i].y * v[i].y + v[i].z * v[i].z + v[i].w * v[i].w;
        }
        #pragma unroll
        for (int o = 16; o; o >>= 1) s += __shfl_xor_sync(0xffffffffu, s, o);
        const float scl = 32.0f / fmaxf(sqrtf(s), 1e-12f);   // sqrt(DIM)=32
        __half2* hh = (__half2*)(g_ha + (size_t)tok * DIM);
        #pragma unroll
        for (int i = 0; i < 8; i++) {
            const float4 g = ((const float4*)gamma)[lane + 32 * i];
            hh[2 * (lane + 32 * i)]     = __floats2half2_rn(v[i].x * scl * g.x, v[i].y * scl * g.y);
            hh[2 * (lane + 32 * i) + 1] = __floats2half2_rn(v[i].z * scl * g.z, v[i].w * scl * g.w);
        }
    } else {
        const size_t i4 = (size_t)(blockIdx.x - RMS_BLOCKS) * 256 + tid;   // EDIM*DIM/4 float4s
        float4 v = ((const float4*)w)[i4];
        ((__half2*)g_wh)[2 * i4]     = __floats2half2_rn(v.x, v.y);
        ((__half2*)g_wh)[2 * i4 + 1] = __floats2half2_rn(v.z, v.w);
    }
}

// ===================== kernel 3: HMMA GEMM, CTA 128x128, 4 warps 64x64 =====
// BK=64, 3-stage cp.async ring, 2 CTAs/SM, register-double-buffered frags,
// cp.async issuance interleaved into the MMA micro-steps, smem-staged epilogue.
#define PITCHB 144                     // 64 fp16 = 128B + 16B pad
#define TILEB  (128 * PITCHB)          // 18432
#define OFF_A  0
#define OFF_B  TILEB
#define STAGEB (2 * TILEB)             // 36864
#define NSTAGE 3
#define NKC    16                      // 1024 / 64
#define GEMM_SMEM (NSTAGE * STAGEB)    // 110592 -> 2 CTAs/SM (216KB/SM)
#define EPITCH 272                     // epilogue smem pitch: 256B data + 16B pad

// One quarter of a stage load: iterations {2p, 2p+1} of the 8-chunk sweep.
__device__ __forceinline__ void load_stage_part(uint32_t sm_stage,
                                                const __half* A, const __half* B,
                                                int koff, int tid, int part) {
    #pragma unroll
    for (int i = 2 * part; i < 2 * part + 2; i++) {
        const int c   = tid + i * 128;       // 0..1023
        const int row = c >> 3;              // 0..127
        const int ch  = c & 7;               // eight 16B chunks per 128B row
        const uint32_t so = (uint32_t)(row * PITCHB + ch * 16);
        const size_t   go = (size_t)row * DIM + koff + ch * 8;
        cp16(sm_stage + OFF_A + so, A + go);
        cp16(sm_stage + OFF_B + so, B + go);
    }
}
__device__ __forceinline__ void load_stage(uint32_t sm_stage,
                                           const __half* A, const __half* B,
                                           int koff, int tid) {
    #pragma unroll
    for (int p = 0; p < 4; p++) load_stage_part(sm_stage, A, B, koff, tid, p);
}

__device__ __forceinline__ void load_frags(uint32_t* ah, uint32_t* bf,
                                           uint32_t sb, uint32_t a_base, uint32_t b_base,
                                           int step) {
    #pragma unroll
    for (int mt = 0; mt < 4; mt++)
        ldm_x4(ah + 4 * mt, sb + OFF_A + a_base + step * 32 + mt * 16 * PITCHB);
    #pragma unroll
    for (int p = 0; p < 4; p++)
        ldm_x4(bf + 4 * p, sb + OFF_B + b_base + step * 32 + p * 16 * PITCHB);
}

__global__ void __launch_bounds__(128, 2) gemm_kernel() {
    extern __shared__ char smem[];
    const uint32_t smem_base = smem_u32(smem);
    const int tid  = threadIdx.x;
    const int wid  = tid >> 5;       // 0..3
    const int lane = tid & 31;
    const int warp_m = wid >> 1;     // 0..1 -> 64-row strip
    const int warp_n = wid & 1;      // 0..1 -> 64-col strip
    const int ntile = blockIdx.x;    // 0..23 (fast dim -> A tile hot in L2)
    const int mtile = blockIdx.y;    // 0..127

    const __half* A = g_ha + (size_t)(mtile * 128) * DIM;
    const __half* B = g_wh + (size_t)(ntile * 128) * DIM;

    load_stage(smem_base + 0 * STAGEB, A, B, 0, tid);
    CP_COMMIT();
    load_stage(smem_base + 1 * STAGEB, A, B, 64, tid);
    CP_COMMIT();

    float acc[4][8][4];
    #pragma unroll
    for (int mt = 0; mt < 4; mt++)
        #pragma unroll
        for (int nt = 0; nt < 8; nt++)
            #pragma unroll
            for (int r = 0; r < 4; r++) acc[mt][nt][r] = 0.f;

    const uint32_t a_base = (uint32_t)((warp_m * 64 + (lane & 15)) * PITCHB) + ((lane >> 4) << 4);
    const uint32_t b_base = (uint32_t)((warp_n * 64 + ((lane >> 4) << 3) + (lane & 7)) * PITCHB)
                          + (((lane >> 3) & 1) << 4);

    uint32_t ah[2][16], bf[2][16];   // double-buffered per micro-step

    CP_WAIT1();                       // stage 0 resident
    __syncthreads();
    load_frags(ah[0], bf[0], smem_base, a_base, b_base, 0);

    int ic = 0;                       // stage index of kc (mod 3)
    for (int kc = 0; kc < NKC; kc++) {
        const uint32_t sb = smem_base + ic * STAGEB;
        const int in = (ic + 1 == NSTAGE) ? 0 : ic + 1;       // stage of kc+1
        const int ir = (in + 1 == NSTAGE) ? 0 : in + 1;       // refill slot = kc+2
        const uint32_t sr = smem_base + ir * STAGEB;
        const bool refill = (kc + 2 < NKC);
        const int koff2 = (kc + 2) * 64;

        // micro-steps 0..2: prefetch next frags + one quarter of the refill, then MMA
        #pragma unroll
        for (int step = 0; step < 3; step++) {
            const int cur = step & 1, nxt = cur ^ 1;
            load_frags(ah[nxt], bf[nxt], sb, a_base, b_base, step + 1);
            if (refill) load_stage_part(sr, A, B, koff2, tid, step);
            #pragma unroll
            for (int nt = 0; nt < 8; nt++)
                #pragma unroll
                for (int mt = 0; mt < 4; mt++)
                    mma16816(acc[mt][nt], &ah[cur][4 * mt], &bf[cur][2 * nt]);
        }
        // final refill quarter + commit, then stage barrier for kc+1
        if (refill) load_stage_part(sr, A, B, koff2, tid, 3);
        CP_COMMIT();
        if (kc + 1 < NKC) {
            CP_WAIT1();
            __syncthreads();
            load_frags(ah[0], bf[0], smem_base + in * STAGEB, a_base, b_base, 0);
        }
        // MMA for micro-step 3 (buf1)
        #pragma unroll
        for (int nt = 0; nt < 8; nt++)
            #pragma unroll
            for (int mt = 0; mt < 4; mt++)
                mma16816(acc[mt][nt], &ah[1][4 * mt], &bf[1][2 * nt]);

        ic = in;
    }

    // ---- epilogue: stage fp16 tile in smem, then fully-coalesced stores ----
    __syncthreads();   // all MMAs done; smem stages free for reuse
    const int gid = lane >> 2, qid = lane & 3;
    #pragma unroll
    for (int mt = 0; mt < 4; mt++) {
        const int r0 = warp_m * 64 + mt * 16 + gid;
        #pragma unroll
        for (int nt = 0; nt < 8; nt++) {
            const int c = warp_n * 64 + nt * 8 + qid * 2;
            *(__half2*)(smem + r0 * EPITCH + c * 2) =
                __floats2half2_rn(acc[mt][nt][0], acc[mt][nt][1]);
            *(__half2*)(smem + (r0 + 8) * EPITCH + c * 2) =
                __floats2half2_rn(acc[mt][nt][2], acc[mt][nt][3]);
        }
    }
    __syncthreads();
    #pragma unroll
    for (int i = 0; i < 16; i++) {
        const int idx = i * 128 + tid;       // 0..2047
        const int row = idx >> 4;
        const int ch  = idx & 15;
        const uint4 v = *(const uint4*)(smem + row * EPITCH + ch * 16);
        *(uint4*)(g_qkva + (size_t)(mtile * 128 + row) * EDIM + ntile * 128 + ch * 8) = v;
    }
}

// ===================== kernel 4: scan pass A (local segment summaries) =====
__global__ void __launch_bounds__(256) scanA_kernel() {
    const int tid = threadIdx.x;
    const int d0  = tid * 4;             // 0..1020
    const int seg = blockIdx.x;
    const int b   = blockIdx.y;
    const size_t tok0 = (size_t)b * SEQ + (size_t)seg * SEGL;
    const __half* base_kv = g_qkva + tok0 * EDIM + DIM + d0;
    const __half* base_av = g_qkva + tok0 * EDIM + 2 * DIM + d0;
    float pa0 = 1.f, pa1 = 1.f, pa2 = 1.f, pa3 = 1.f;
    float y0 = 0.f, y1 = 0.f, y2 = 0.f, y3 = 0.f;
    #pragma unroll
    for (int i = 0; i < SEGL; i++) {
        const uint2 kvr = __ldg((const uint2*)(base_kv + (size_t)i * EDIM));
        const uint2 avr = __ldg((const uint2*)(base_av + (size_t)i * EDIM));
        const float2 kv01 = __half22float2(*(const __half2*)&kvr.x);
        const float2 kv23 = __half22float2(*(const __half2*)&kvr.y);
        const float2 av01 = __half22float2(*(const __half2*)&avr.x);
        const float2 av23 = __half22float2(*(const __half2*)&avr.y);
        const float a0 = 1.0f / (1.0f + __expf(-av01.x));
        const float a1 = 1.0f / (1.0f + __expf(-av01.y));
        const float a2 = 1.0f / (1.0f + __expf(-av23.x));
        const float a3 = 1.0f / (1.0f + __expf(-av23.y));
        y0 = a0 * y0 + kv01.x;  pa0 *= a0;
        y1 = a1 * y1 + kv01.y;  pa1 *= a1;
        y2 = a2 * y2 + kv23.x;  pa2 *= a2;
        y3 = a3 * y3 + kv23.y;  pa3 *= a3;
    }
    const size_t sidx = (size_t)(b * NSEG + seg) * DIM + d0;
    *(float4*)&g_sumA[sidx] = make_float4(pa0, pa1, pa2, pa3);
    *(float4*)&g_sumY[sidx] = make_float4(y0, y1, y2, y3);
}

// ===================== kernel 5: scan pass B — Kogge-Stone parallel scan ===
__global__ void __launch_bounds__(256) scanB_kernel() {
    const int tid  = threadIdx.x;
    const int col  = tid >> 7;           // 0..1
    const int s    = tid & 127;          // segment
    const int lane = s & 31;
    const int wc   = s >> 5;             // warp index within column (0..3)
    const int d    = blockIdx.x * 2 + col;
    const int b    = blockIdx.y;
    const size_t idx = (size_t)(b * NSEG + s) * DIM + d;

    float a = g_sumA[idx];
    float y = g_sumY[idx];

    #pragma unroll
    for (int off = 1; off < 32; off <<= 1) {
        const float ap = __shfl_up_sync(0xffffffffu, a, off);
        const float yp = __shfl_up_sync(0xffffffffu, y, off);
        if (lane >= off) { y = a * yp + y; a = a * ap; }
    }

    __shared__ float sA[2][4], sY[2][4], sI[2][128];
    if (lane == 31) { sA[col][wc] = a; sY[col][wc] = y; }
    __syncthreads();
    float Yp = 0.f;
    for (int ww = 0; ww < wc; ww++) {
        Yp = sA[col][ww] * Yp + sY[col][ww];
    }
    y = a * Yp + y;   // global inclusive value for segment s

    sI[col][s] = y;
    __syncthreads();
    g_carry[idx] = (s == 0) ? 0.f : sI[col][s - 1];
}

// ===================== kernel 6: scan pass C (recompute + q*y) =============
__global__ void __launch_bounds__(256) scanC_kernel(float* __restrict__ out) {
    const int tid = threadIdx.x;
    const int d0  = tid * 4;
    const int seg = blockIdx.x;
    const int b   = blockIdx.y;
    const size_t tok0 = (size_t)b * SEQ + (size_t)seg * SEGL;
    const __half* base_q  = g_qkva + tok0 * EDIM + d0;
    const __half* base_kv = g_qkva + tok0 * EDIM + DIM + d0;
    const __half* base_av = g_qkva + tok0 * EDIM + 2 * DIM + d0;
    float* outp = out + tok0 * DIM + d0;
    const float4 cin = *(const float4*)&g_carry[(size_t)(b * NSEG + seg) * DIM + d0];
    float y0 = cin.x, y1 = cin.y, y2 = cin.z, y3 = cin.w;
    #pragma unroll
    for (int i = 0; i < SEGL; i++) {
        const uint2 kvr = __ldg((const uint2*)(base_kv + (size_t)i * EDIM));
        const uint2 avr = __ldg((const uint2*)(base_av + (size_t)i * EDIM));
        const uint2 qr  = __ldg((const uint2*)(base_q  + (size_t)i * EDIM));
        const float2 kv01 = __half22float2(*(const __half2*)&kvr.x);
        const float2 kv23 = __half22float2(*(const __half2*)&kvr.y);
        const float2 av01 = __half22float2(*(const __half2*)&avr.x);
        const float2 av23 = __half22float2(*(const __half2*)&avr.y);
        const float2 q01  = __half22float2(*(const __half2*)&qr.x);
        const float2 q23  = __half22float2(*(const __half2*)&qr.y);
        const float a0 = 1.0f / (1.0f + __expf(-av01.x));
        const float a1 = 1.0f / (1.0f + __expf(-av01.y));
        const float a2 = 1.0f / (1.0f + __expf(-av23.x));
        const float a3 = 1.0f / (1.0f + __expf(-av23.y));
        y0 = a0 * y0 + kv01.x;
        y1 = a1 * y1 + kv01.y;
        y2 = a2 * y2 + kv23.x;
        y3 = a3 * y3 + kv23.y;
        const float4 o = make_float4(q01.x * y0, q01.y * y1, q23.x * y2, q23.y * y3);
        __stcs((float4*)(outp + (size_t)i * DIM), o);
    }
}

// ===================== launcher =====================
extern "C" void kernel_launch(void* const* d_in, const int* in_sizes, int n_in,
                              void* d_out, int out_size) {
    const float* x     = (const float*)d_in[0];   // [4,4096,1024] f32
    const float* w     = (const float*)d_in[1];   // [3072,1024]  f32
    const float* gamma = (const float*)d_in[2];   // [1024]       f32
    float* out = (float*)d_out;

    cudaFuncSetAttribute(gemm_kernel, cudaFuncAttributeMaxDynamicSharedMemorySize, GEMM_SMEM);

    prep_kernel<<<RMS_BLOCKS + (EDIM * DIM / 4) / 256, 256>>>(x, w, gamma);
    gemm_kernel<<<dim3(EDIM / 128, NTOK / 128), 128, GEMM_SMEM>>>();
    scanA_kernel<<<dim3(NSEG, BATCH), 256>>>();
    scanB_kernel<<<dim3(DIM / 2, BATCH), 256>>>();
    scanC_kernel<<<dim3(NSEG, BATCH), 256>>>(out);
}